// round 1
// baseline (speedup 1.0000x reference)
#include <cuda_runtime.h>
#include <cstddef>

// ---------------- scratch (static __device__, no allocs) ----------------
__device__ float g_feas[3 * 512 * 1024];
__device__ float g_bsum[3 * 512];
__device__ float g_att[3 * 512];
__device__ float g_outres[512 * 1024];
__device__ float g_fgs[512 * 256];
__device__ float g_P[256 * 4608];
__device__ float g_PT[4608 * 256];
__device__ float g_pnorm[256];
__device__ float g_S[8 * 256 * 256];      // split-K partials of score
__device__ float g_attnP[256 * 256];      // attn[p][q]
__device__ float g_bgbig[8192 * 256];     // (ki,kj,c) x p gather of bg
__device__ float g_T[8192 * 256];         // deconv partials
__device__ float g_out32T[1024 * 512];    // post-RAL out_32, pixel-major
__device__ float g_z[1024 * 1024];        // concat(gus_out, out_csa)
__device__ float g_d1[512 * 1024];
__device__ float g_z2[1024 * 1024];       // concat(leaky(norm(down)), out_res)

// ---------------- helpers ----------------
__device__ __forceinline__ void blockReduce2(float& s, float& s2, float* sm) {
    __syncthreads();
    int tid = threadIdx.x;
    #pragma unroll
    for (int o = 16; o > 0; o >>= 1) {
        s  += __shfl_down_sync(0xFFFFFFFFu, s, o);
        s2 += __shfl_down_sync(0xFFFFFFFFu, s2, o);
    }
    int w = tid >> 5, l = tid & 31;
    int nw = blockDim.x >> 5;
    if (l == 0) { sm[w] = s; sm[32 + w] = s2; }
    __syncthreads();
    if (tid < 32) {
        s  = (tid < nw) ? sm[tid] : 0.f;
        s2 = (tid < nw) ? sm[32 + tid] : 0.f;
        #pragma unroll
        for (int o = 16; o > 0; o >>= 1) {
            s  += __shfl_down_sync(0xFFFFFFFFu, s, o);
            s2 += __shfl_down_sync(0xFFFFFFFFu, s2, o);
        }
        if (tid == 0) { sm[0] = s; sm[32] = s2; }
    }
    __syncthreads();
    s = sm[0]; s2 = sm[32];
}

// ---------------- 1) SK grouped conv + instance norm + relu ----------------
template <int KS>
__global__ __launch_bounds__(256) void sk_conv_kernel(
    const float* __restrict__ x, const float* __restrict__ w,
    const float* __restrict__ bias, int branch) {
    constexpr int PAD = KS / 2;
    int oc = blockIdx.x;
    __shared__ float s_ch[1024];
    __shared__ float s_w[16 * KS * KS];
    __shared__ float s_red[64];
    int tid = threadIdx.x;
    const float* xin = x + (size_t)(oc >> 4) * 16 * 1024;
    const float* wo = w + (size_t)oc * 16 * KS * KS;
    for (int i = tid; i < 16 * KS * KS; i += 256) s_w[i] = wo[i];

    float acc[4] = {0.f, 0.f, 0.f, 0.f};
    for (int ic = 0; ic < 16; ic++) {
        __syncthreads();
        for (int i = tid; i < 1024; i += 256) s_ch[i] = xin[ic * 1024 + i];
        __syncthreads();
        const float* wi = &s_w[ic * KS * KS];
        #pragma unroll
        for (int q = 0; q < 4; q++) {
            int p = tid + q * 256;
            int y = p >> 5, xx = p & 31;
            float a = acc[q];
            #pragma unroll
            for (int ky = 0; ky < KS; ky++) {
                int iy = y + ky - PAD;
                if ((unsigned)iy < 32u) {
                    #pragma unroll
                    for (int kx = 0; kx < KS; kx++) {
                        int ix = xx + kx - PAD;
                        if ((unsigned)ix < 32u)
                            a += s_ch[iy * 32 + ix] * wi[ky * KS + kx];
                    }
                }
            }
            acc[q] = a;
        }
    }
    float b = bias[oc];
    float s = 0.f, s2 = 0.f;
    #pragma unroll
    for (int q = 0; q < 4; q++) { acc[q] += b; s += acc[q]; s2 += acc[q] * acc[q]; }
    blockReduce2(s, s2, s_red);
    float mu = s * (1.f / 1024.f);
    float var = s2 * (1.f / 1024.f) - mu * mu;
    float inv = rsqrtf(var + 1e-5f);
    float rs = 0.f;
    float* fo = &g_feas[(size_t)branch * 512 * 1024 + (size_t)oc * 1024];
    #pragma unroll
    for (int q = 0; q < 4; q++) {
        float r = (acc[q] - mu) * inv;
        r = fmaxf(r, 0.f);
        fo[tid + q * 256] = r;
        rs += r;
    }
    float dummy = 0.f;
    blockReduce2(rs, dummy, s_red);
    if (tid == 0) g_bsum[branch * 512 + oc] = rs;
}

// ---------------- 2) SK attention (FC chain + softmax over 3 branches) ----------------
__global__ __launch_bounds__(512) void att_kernel(
    const float* __restrict__ w_fc, const float* __restrict__ b_fc,
    const float* __restrict__ w0, const float* __restrict__ b0,
    const float* __restrict__ w1, const float* __restrict__ b1,
    const float* __restrict__ w2, const float* __restrict__ b2) {
    __shared__ float fs[512];
    __shared__ float fz[32];
    int t = threadIdx.x;
    fs[t] = (g_bsum[t] + g_bsum[512 + t] + g_bsum[1024 + t]) * (1.f / 1024.f);
    __syncthreads();
    if (t < 32) {
        float a = b_fc[t];
        for (int c = 0; c < 512; c++) a += fs[c] * w_fc[t * 512 + c];
        fz[t] = a;
    }
    __syncthreads();
    float a0 = b0[t], a1 = b1[t], a2 = b2[t];
    #pragma unroll
    for (int j = 0; j < 32; j++) {
        float zz = fz[j];
        a0 += zz * w0[t * 32 + j];
        a1 += zz * w1[t * 32 + j];
        a2 += zz * w2[t * 32 + j];
    }
    float mx = fmaxf(a0, fmaxf(a1, a2));
    float e0 = __expf(a0 - mx), e1 = __expf(a1 - mx), e2 = __expf(a2 - mx);
    float inv = 1.f / (e0 + e1 + e2);
    g_att[t] = e0 * inv; g_att[512 + t] = e1 * inv; g_att[1024 + t] = e2 * inv;
}

// ---------------- 3) combine branches -> out_res; 2x2 avg pool -> fg_small ----------------
__global__ __launch_bounds__(256) void combine_kernel() {
    int c = blockIdx.x, tid = threadIdx.x;
    float a0 = g_att[c], a1 = g_att[512 + c], a2 = g_att[1024 + c];
    __shared__ float s_o[1024];
    for (int i = tid; i < 1024; i += 256) {
        float v = a0 * g_feas[(size_t)c * 1024 + i]
                + a1 * g_feas[512 * 1024 + (size_t)c * 1024 + i]
                + a2 * g_feas[2 * 512 * 1024 + (size_t)c * 1024 + i];
        g_outres[c * 1024 + i] = v;
        s_o[i] = v;
    }
    __syncthreads();
    int py = tid >> 4, px = tid & 15;
    float p = 0.25f * (s_o[(2 * py) * 32 + 2 * px] + s_o[(2 * py) * 32 + 2 * px + 1] +
                       s_o[(2 * py + 1) * 32 + 2 * px] + s_o[(2 * py + 1) * 32 + 2 * px + 1]);
    g_fgs[c * 256 + tid] = p;
}

// ---------------- 4) build patch matrix P (256x4608), PT, norms ----------------
__global__ __launch_bounds__(256) void patch_kernel() {
    __shared__ float s_red[64];
    int p = blockIdx.x;
    int py = p >> 4, px = p & 15;
    int tid = threadIdx.x;
    float ss = 0.f;
    for (int k = tid; k < 4608; k += 256) {
        int c = k / 9, ij = k - c * 9;
        int di = ij / 3, dj = ij - di * 3;
        int y = py + di - 1, x = px + dj - 1;
        float v = 0.f;
        if ((unsigned)y < 16u && (unsigned)x < 16u) v = g_fgs[c * 256 + y * 16 + x];
        g_P[(size_t)p * 4608 + k] = v;
        g_PT[(size_t)k * 256 + p] = v;
        ss += v * v;
    }
    float dummy = 0.f;
    blockReduce2(ss, dummy, s_red);
    if (tid == 0) g_pnorm[p] = fmaxf(sqrtf(ss), 1e-4f);
}

// ---------------- generic SGEMM  C = A(MxK) * B(KxN), row-major, dims % (64,64,16)==0 ----------------
__global__ __launch_bounds__(256) void sgemm_kernel(
    const float* __restrict__ A, const float* __restrict__ B, float* __restrict__ C,
    int M, int N, int K, int ksplit) {
    __shared__ float As[16][64];
    __shared__ float Bs[16][64];
    int tid = threadIdx.x;
    int bn = blockIdx.x * 64;
    int bm = blockIdx.y * 64;
    int kchunk = K / ksplit;
    int k0 = blockIdx.z * kchunk;
    C += (size_t)blockIdx.z * M * N;
    int tx = tid & 15, ty = tid >> 4;
    int ar = tid >> 2, ac = (tid & 3) * 4;
    int brr = tid >> 4, bc = (tid & 15) * 4;
    float acc[4][4] = {};
    for (int kk = k0; kk < k0 + kchunk; kk += 16) {
        float4 av = *(const float4*)(A + (size_t)(bm + ar) * K + kk + ac);
        As[ac + 0][ar] = av.x; As[ac + 1][ar] = av.y;
        As[ac + 2][ar] = av.z; As[ac + 3][ar] = av.w;
        float4 bv = *(const float4*)(B + (size_t)(kk + brr) * N + bn + bc);
        *(float4*)&Bs[brr][bc] = bv;
        __syncthreads();
        #pragma unroll
        for (int k = 0; k < 16; k++) {
            float4 ra = *(const float4*)&As[k][ty * 4];
            float4 rb = *(const float4*)&Bs[k][tx * 4];
            acc[0][0] += ra.x * rb.x; acc[0][1] += ra.x * rb.y; acc[0][2] += ra.x * rb.z; acc[0][3] += ra.x * rb.w;
            acc[1][0] += ra.y * rb.x; acc[1][1] += ra.y * rb.y; acc[1][2] += ra.y * rb.z; acc[1][3] += ra.y * rb.w;
            acc[2][0] += ra.z * rb.x; acc[2][1] += ra.z * rb.y; acc[2][2] += ra.z * rb.z; acc[2][3] += ra.z * rb.w;
            acc[3][0] += ra.w * rb.x; acc[3][1] += ra.w * rb.y; acc[3][2] += ra.w * rb.z; acc[3][3] += ra.w * rb.w;
        }
        __syncthreads();
    }
    #pragma unroll
    for (int i = 0; i < 4; i++) {
        float4 v = make_float4(acc[i][0], acc[i][1], acc[i][2], acc[i][3]);
        *(float4*)(C + (size_t)(bm + ty * 4 + i) * N + bn + tx * 4) = v;
    }
}

// ---------------- 6) softmax over p per q (sums split-K partials, folds 10/norm) ----------------
__global__ __launch_bounds__(256) void ral_softmax_kernel(int ksplit) {
    int q = blockIdx.x;
    int p = threadIdx.x;
    __shared__ float red[256];
    float v = 0.f;
    for (int z = 0; z < ksplit; z++) v += g_S[(size_t)z * 65536 + p * 256 + q];
    v = v * 10.f / g_pnorm[p];
    red[p] = v; __syncthreads();
    for (int s = 128; s > 0; s >>= 1) { if (p < s) red[p] = fmaxf(red[p], red[p + s]); __syncthreads(); }
    float mx = red[0]; __syncthreads();
    float e = __expf(v - mx);
    red[p] = e; __syncthreads();
    for (int s = 128; s > 0; s >>= 1) { if (p < s) red[p] += red[p + s]; __syncthreads(); }
    float inv = 1.f / red[0];
    g_attnP[p * 256 + q] = e * inv;
}

// ---------------- 7) gather bg into (16 taps x 512 ch) x 256 patch matrix ----------------
__global__ __launch_bounds__(256) void bgbig_kernel() {
    int row = blockIdx.x;            // combo*512 + c
    int combo = row >> 9;
    int c = row & 511;
    int ki = combo >> 2, kj = combo & 3;
    int p = threadIdx.x;
    int py = p >> 4, px = p & 15;
    int r = 2 * py + ki - 1, col = 2 * px + kj - 1;
    float v = 0.f;
    if ((unsigned)r < 32u && (unsigned)col < 32u) v = g_outres[c * 1024 + r * 32 + col];
    g_bgbig[(size_t)row * 256 + p] = v;
}

// ---------------- 9) scatter transposed-conv taps -> post-RAL out_32 (pixel-major) ----------------
__global__ __launch_bounds__(256) void ral_out_kernel() {
    int c = blockIdx.x;
    int tid = threadIdx.x;
    #pragma unroll
    for (int q = 0; q < 4; q++) {
        int pix = tid + q * 256;
        int ho = pix >> 5, wo = pix & 31;
        float acc = 0.f;
        for (int ki = (ho + 1) & 1; ki < 4; ki += 2) {
            int qy = (ho + 1 - ki) >> 1;
            if ((unsigned)qy >= 16u) continue;
            for (int kj = (wo + 1) & 1; kj < 4; kj += 2) {
                int qx = (wo + 1 - kj) >> 1;
                if ((unsigned)qx >= 16u) continue;
                acc += g_T[(size_t)((ki * 4 + kj) * 512 + c) * 256 + qy * 16 + qx];
            }
        }
        g_out32T[(size_t)pix * 512 + c] = acc * 0.25f;
    }
}

// ---------------- 11) CSA: per-position 3x3 patch softmax ----------------
__global__ __launch_bounds__(512) void csa_kernel() {
    int pos = blockIdx.x;
    int y = pos >> 5, x = pos & 31;
    int c = threadIdx.x;
    __shared__ float s_sum[16 * 9];
    __shared__ float s_a[9];
    float center = g_out32T[(size_t)pos * 512 + c];
    float sc = 1.f / (1.f + __expf(-center));
    float nb[9], pr[9];
    #pragma unroll
    for (int ij = 0; ij < 9; ij++) {
        int di = ij / 3 - 1, dj = ij % 3 - 1;
        int yy = y + di, xx = x + dj;
        bool ok = (unsigned)yy < 32u && (unsigned)xx < 32u;
        float v = ok ? g_out32T[(size_t)(yy * 32 + xx) * 512 + c] : 0.f;
        nb[ij] = v;
        float sn = ok ? 1.f / (1.f + __expf(-v)) : 0.f;
        pr[ij] = sc * sn;
    }
    #pragma unroll
    for (int ij = 0; ij < 9; ij++)
        #pragma unroll
        for (int o = 16; o > 0; o >>= 1) pr[ij] += __shfl_down_sync(0xFFFFFFFFu, pr[ij], o);
    int w = c >> 5, l = c & 31;
    if (l == 0) {
        #pragma unroll
        for (int ij = 0; ij < 9; ij++) s_sum[w * 9 + ij] = pr[ij];
    }
    __syncthreads();
    if (c < 9) {
        float t = 0.f;
        for (int w2 = 0; w2 < 16; w2++) t += s_sum[w2 * 9 + c];
        s_a[c] = t * (1.f / 512.f);
    }
    __syncthreads();
    if (c == 0) {
        float mx = s_a[0];
        for (int ij = 1; ij < 9; ij++) mx = fmaxf(mx, s_a[ij]);
        float sum = 0.f; float e[9];
        for (int ij = 0; ij < 9; ij++) { e[ij] = __expf(s_a[ij] - mx); sum += e[ij]; }
        float invs = 1.f / sum;
        for (int ij = 0; ij < 9; ij++) s_a[ij] = e[ij] * invs;
    }
    __syncthreads();
    float out = 0.f;
    #pragma unroll
    for (int ij = 0; ij < 9; ij++) out += s_a[ij] * nb[ij];
    // reshape quirk: store row-major (pos, c) into second half of z
    g_z[512 * 1024 + (size_t)pos * 512 + c] = out;
}

// ---------------- instance norm + leaky relu (+optional concat copy) ----------------
__global__ __launch_bounds__(256) void norm_leaky_kernel(
    const float* __restrict__ in, float* __restrict__ outA,
    const float* __restrict__ cpsrc, float* __restrict__ outB) {
    __shared__ float s_red[64];
    int c = blockIdx.x, tid = threadIdx.x;
    float v[4]; float s = 0.f, s2 = 0.f;
    #pragma unroll
    for (int q = 0; q < 4; q++) {
        v[q] = in[c * 1024 + tid + q * 256];
        s += v[q]; s2 += v[q] * v[q];
    }
    blockReduce2(s, s2, s_red);
    float mu = s * (1.f / 1024.f);
    float inv = rsqrtf(s2 * (1.f / 1024.f) - mu * mu + 1e-5f);
    #pragma unroll
    for (int q = 0; q < 4; q++) {
        float f = (v[q] - mu) * inv;
        outA[c * 1024 + tid + q * 256] = f >= 0.f ? f : 0.2f * f;
    }
    if (cpsrc != nullptr) {
        #pragma unroll
        for (int q = 0; q < 4; q++)
            outB[c * 1024 + tid + q * 256] = cpsrc[c * 1024 + tid + q * 256];
    }
}

// ---------------- host ----------------
extern "C" void kernel_launch(void* const* d_in, const int* in_sizes, int n_in,
                              void* d_out, int out_size) {
    const float* x     = (const float*)d_in[0];
    const float* gus   = (const float*)d_in[1];
    const float* w_sk3 = (const float*)d_in[2];
    const float* b_sk3 = (const float*)d_in[3];
    const float* w_sk5 = (const float*)d_in[4];
    const float* b_sk5 = (const float*)d_in[5];
    const float* w_sk7 = (const float*)d_in[6];
    const float* b_sk7 = (const float*)d_in[7];
    const float* w_fc  = (const float*)d_in[8];
    const float* b_fc  = (const float*)d_in[9];
    const float* w_fc0 = (const float*)d_in[10];
    const float* b_fc0 = (const float*)d_in[11];
    const float* w_fc1 = (const float*)d_in[12];
    const float* b_fc1 = (const float*)d_in[13];
    const float* w_fc2 = (const float*)d_in[14];
    const float* b_fc2 = (const float*)d_in[15];
    const float* w_down = (const float*)d_in[16];
    const float* w_fuse = (const float*)d_in[17];

    float *P, *PT, *S, *attnP, *bgbig, *T, *out32T, *z, *d1, *z2, *outres;
    cudaGetSymbolAddress((void**)&P, g_P);
    cudaGetSymbolAddress((void**)&PT, g_PT);
    cudaGetSymbolAddress((void**)&S, g_S);
    cudaGetSymbolAddress((void**)&attnP, g_attnP);
    cudaGetSymbolAddress((void**)&bgbig, g_bgbig);
    cudaGetSymbolAddress((void**)&T, g_T);
    cudaGetSymbolAddress((void**)&out32T, g_out32T);
    cudaGetSymbolAddress((void**)&z, g_z);
    cudaGetSymbolAddress((void**)&d1, g_d1);
    cudaGetSymbolAddress((void**)&z2, g_z2);
    cudaGetSymbolAddress((void**)&outres, g_outres);

    // SKConv branches (conv + IN + relu + pixel sums)
    sk_conv_kernel<3><<<512, 256>>>(x, w_sk3, b_sk3, 0);
    sk_conv_kernel<5><<<512, 256>>>(x, w_sk5, b_sk5, 1);
    sk_conv_kernel<7><<<512, 256>>>(x, w_sk7, b_sk7, 2);
    // channel attention
    att_kernel<<<1, 512>>>(w_fc, b_fc, w_fc0, b_fc0, w_fc1, b_fc1, w_fc2, b_fc2);
    // weighted combine -> out_res, fg_small
    combine_kernel<<<512, 256>>>();
    // RAL: patches, score GEMM (split-K 8), softmax, deconv-as-GEMM
    patch_kernel<<<256, 256>>>();
    sgemm_kernel<<<dim3(4, 4, 8), 256>>>(P, PT, S, 256, 256, 4608, 8);
    ral_softmax_kernel<<<256, 256>>>(8);
    bgbig_kernel<<<8192, 256>>>();
    sgemm_kernel<<<dim3(4, 128, 1), 256>>>(bgbig, attnP, T, 8192, 256, 256, 1);
    ral_out_kernel<<<512, 256>>>();
    // gaussian einsum -> first half of z (reshape is flat reinterpret)
    sgemm_kernel<<<dim3(8, 16, 1), 256>>>(gus, out32T, z, 1024, 512, 1024, 1);
    // CSA -> second half of z
    csa_kernel<<<1024, 512>>>();
    // down 1x1 conv + IN + leaky, concat out_res
    sgemm_kernel<<<dim3(16, 8, 1), 256>>>(w_down, z, d1, 512, 1024, 1024, 1);
    norm_leaky_kernel<<<512, 256>>>(d1, z2, outres, z2 + 512 * 1024);
    // fuse 1x1 conv + IN + leaky -> output
    sgemm_kernel<<<dim3(16, 8, 1), 256>>>(w_fuse, z2, d1, 512, 1024, 1024, 1);
    norm_leaky_kernel<<<512, 256>>>(d1, (float*)d_out, nullptr, nullptr);
}

// round 2
// speedup vs baseline: 1.2329x; 1.2329x over previous
#include <cuda_runtime.h>
#include <cstddef>

// ---------------- scratch (static __device__, no allocs) ----------------
__device__ float g_feas[3 * 512 * 1024];
__device__ float g_bsum[3 * 512];
__device__ float g_att[3 * 512];
__device__ float g_outres[512 * 1024];
__device__ float g_fgs[512 * 256];
__device__ float g_P[256 * 4608];
__device__ float g_pnorm[256];
__device__ float g_S[32 * 256 * 256];     // split-K partials of score (symmetric)
__device__ float g_attnT[256 * 256];      // attn transposed: [q][p]
__device__ float g_bgbig[8192 * 256];     // (ki,kj,c) x p gather of bg
__device__ float g_T[256 * 8192];         // T'[q][row]; reused for gaussian partials
__device__ float g_out32T[1024 * 512];    // post-RAL out_32, pixel-major
__device__ float g_z[1024 * 1024];        // concat(gus_out, out_csa)
__device__ float g_d1[4 * 512 * 1024];    // split-K partials of down/fuse
__device__ float g_z2[1024 * 1024];       // concat(leaky(norm(down)), out_res)

// ---------------- helpers ----------------
__device__ __forceinline__ void blockReduce2(float& s, float& s2, float* sm) {
    __syncthreads();
    int tid = threadIdx.x;
    #pragma unroll
    for (int o = 16; o > 0; o >>= 1) {
        s  += __shfl_down_sync(0xFFFFFFFFu, s, o);
        s2 += __shfl_down_sync(0xFFFFFFFFu, s2, o);
    }
    int w = tid >> 5, l = tid & 31;
    int nw = blockDim.x >> 5;
    if (l == 0) { sm[w] = s; sm[32 + w] = s2; }
    __syncthreads();
    if (tid < 32) {
        s  = (tid < nw) ? sm[tid] : 0.f;
        s2 = (tid < nw) ? sm[32 + tid] : 0.f;
        #pragma unroll
        for (int o = 16; o > 0; o >>= 1) {
            s  += __shfl_down_sync(0xFFFFFFFFu, s, o);
            s2 += __shfl_down_sync(0xFFFFFFFFu, s2, o);
        }
        if (tid == 0) { sm[0] = s; sm[32] = s2; }
    }
    __syncthreads();
    s = sm[0]; s2 = sm[32];
}

// ---------------- 1) SK grouped conv + instance norm + relu ----------------
template <int KS>
__global__ __launch_bounds__(256) void sk_conv_kernel(
    const float* __restrict__ x, const float* __restrict__ w,
    const float* __restrict__ bias, int branch) {
    constexpr int PAD = KS / 2;
    int oc = blockIdx.x;
    __shared__ float s_ch[1024];
    __shared__ float s_w[16 * KS * KS];
    __shared__ float s_red[64];
    int tid = threadIdx.x;
    const float* xin = x + (size_t)(oc >> 4) * 16 * 1024;
    const float* wo = w + (size_t)oc * 16 * KS * KS;
    for (int i = tid; i < 16 * KS * KS; i += 256) s_w[i] = wo[i];

    float acc[4] = {0.f, 0.f, 0.f, 0.f};
    for (int ic = 0; ic < 16; ic++) {
        __syncthreads();
        for (int i = tid; i < 1024; i += 256) s_ch[i] = xin[ic * 1024 + i];
        __syncthreads();
        const float* wi = &s_w[ic * KS * KS];
        #pragma unroll
        for (int q = 0; q < 4; q++) {
            int p = tid + q * 256;
            int y = p >> 5, xx = p & 31;
            float a = acc[q];
            #pragma unroll
            for (int ky = 0; ky < KS; ky++) {
                int iy = y + ky - PAD;
                if ((unsigned)iy < 32u) {
                    #pragma unroll
                    for (int kx = 0; kx < KS; kx++) {
                        int ix = xx + kx - PAD;
                        if ((unsigned)ix < 32u)
                            a += s_ch[iy * 32 + ix] * wi[ky * KS + kx];
                    }
                }
            }
            acc[q] = a;
        }
    }
    float b = bias[oc];
    float s = 0.f, s2 = 0.f;
    #pragma unroll
    for (int q = 0; q < 4; q++) { acc[q] += b; s += acc[q]; s2 += acc[q] * acc[q]; }
    blockReduce2(s, s2, s_red);
    float mu = s * (1.f / 1024.f);
    float var = s2 * (1.f / 1024.f) - mu * mu;
    float inv = rsqrtf(var + 1e-5f);
    float rs = 0.f;
    float* fo = &g_feas[(size_t)branch * 512 * 1024 + (size_t)oc * 1024];
    #pragma unroll
    for (int q = 0; q < 4; q++) {
        float r = (acc[q] - mu) * inv;
        r = fmaxf(r, 0.f);
        fo[tid + q * 256] = r;
        rs += r;
    }
    float dummy = 0.f;
    blockReduce2(rs, dummy, s_red);
    if (tid == 0) g_bsum[branch * 512 + oc] = rs;
}

// ---------------- 2) SK attention (parallelized FC chain + branch softmax) ----------------
__global__ __launch_bounds__(512) void att_kernel(
    const float* __restrict__ w_fc, const float* __restrict__ b_fc,
    const float* __restrict__ w0, const float* __restrict__ b0,
    const float* __restrict__ w1, const float* __restrict__ b1,
    const float* __restrict__ w2, const float* __restrict__ b2) {
    __shared__ float fs[512];
    __shared__ float fz[32];
    int t = threadIdx.x;
    fs[t] = (g_bsum[t] + g_bsum[512 + t] + g_bsum[1024 + t]) * (1.f / 1024.f);
    __syncthreads();
    // FC1: 32 outputs x 512 inputs; 16 threads per output
    int j = t >> 4, sub = t & 15;
    float a = 0.f;
    #pragma unroll
    for (int i = 0; i < 32; i++) {
        int c = sub * 32 + i;
        a += fs[c] * w_fc[j * 512 + c];
    }
    #pragma unroll
    for (int o = 8; o > 0; o >>= 1) a += __shfl_down_sync(0xFFFFFFFFu, a, o, 16);
    if (sub == 0) fz[j] = a + b_fc[j];
    __syncthreads();
    float a0 = b0[t], a1 = b1[t], a2 = b2[t];
    #pragma unroll
    for (int jj = 0; jj < 32; jj++) {
        float zz = fz[jj];
        a0 += zz * w0[t * 32 + jj];
        a1 += zz * w1[t * 32 + jj];
        a2 += zz * w2[t * 32 + jj];
    }
    float mx = fmaxf(a0, fmaxf(a1, a2));
    float e0 = __expf(a0 - mx), e1 = __expf(a1 - mx), e2 = __expf(a2 - mx);
    float inv = 1.f / (e0 + e1 + e2);
    g_att[t] = e0 * inv; g_att[512 + t] = e1 * inv; g_att[1024 + t] = e2 * inv;
}

// ---------------- 3) combine branches -> out_res; 2x2 avg pool -> fg_small ----------------
__global__ __launch_bounds__(256) void combine_kernel() {
    int c = blockIdx.x, tid = threadIdx.x;
    float a0 = g_att[c], a1 = g_att[512 + c], a2 = g_att[1024 + c];
    __shared__ float s_o[1024];
    for (int i = tid; i < 1024; i += 256) {
        float v = a0 * g_feas[(size_t)c * 1024 + i]
                + a1 * g_feas[512 * 1024 + (size_t)c * 1024 + i]
                + a2 * g_feas[2 * 512 * 1024 + (size_t)c * 1024 + i];
        g_outres[c * 1024 + i] = v;
        s_o[i] = v;
    }
    __syncthreads();
    int py = tid >> 4, px = tid & 15;
    float p = 0.25f * (s_o[(2 * py) * 32 + 2 * px] + s_o[(2 * py) * 32 + 2 * px + 1] +
                       s_o[(2 * py + 1) * 32 + 2 * px] + s_o[(2 * py + 1) * 32 + 2 * px + 1]);
    g_fgs[c * 256 + tid] = p;
}

// ---------------- 4) build patch matrix P (256x4608) + norms ----------------
__global__ __launch_bounds__(256) void patch_kernel() {
    __shared__ float s_red[64];
    int p = blockIdx.x;
    int py = p >> 4, px = p & 15;
    int tid = threadIdx.x;
    float ss = 0.f;
    for (int k = tid; k < 4608; k += 256) {
        int c = k / 9, ij = k - c * 9;
        int di = ij / 3, dj = ij - di * 3;
        int y = py + di - 1, x = px + dj - 1;
        float v = 0.f;
        if ((unsigned)y < 16u && (unsigned)x < 16u) v = g_fgs[c * 256 + y * 16 + x];
        g_P[(size_t)p * 4608 + k] = v;
        ss += v * v;
    }
    float dummy = 0.f;
    blockReduce2(ss, dummy, s_red);
    if (tid == 0) g_pnorm[p] = fmaxf(sqrtf(ss), 1e-4f);
}

// ---- 128x128-tile SGEMM, 8x8 per thread.  BT=false: C=A(MxK)*B(KxN);
//      BT=true:  C=A(MxK)*B(NxK)^T.  All row-major; M,N %128==0, kchunk %16==0. ----
template <bool BT>
__global__ __launch_bounds__(256) void gemm128(
    const float* __restrict__ A, const float* __restrict__ B, float* __restrict__ C,
    int M, int N, int K, int ksplit) {
    __shared__ float As[16][132];
    __shared__ float Bs[16][132];
    int tid = threadIdx.x;
    int bm = blockIdx.y * 128, bn = blockIdx.x * 128;
    int kchunk = K / ksplit, k0 = blockIdx.z * kchunk;
    C += (size_t)blockIdx.z * M * N;
    int lr = tid >> 2, lc = (tid & 3) * 4;
    int brow = tid >> 5, bcol = (tid & 31) * 4;
    int tx = tid & 15, ty = tid >> 4;
    float acc[8][8] = {};
    for (int kk = k0; kk < k0 + kchunk; kk += 16) {
        #pragma unroll
        for (int h = 0; h < 2; h++) {
            int r = lr + h * 64;
            float4 v = *(const float4*)(A + (size_t)(bm + r) * K + kk + lc);
            As[lc + 0][r] = v.x; As[lc + 1][r] = v.y;
            As[lc + 2][r] = v.z; As[lc + 3][r] = v.w;
        }
        if (BT) {
            #pragma unroll
            for (int h = 0; h < 2; h++) {
                int n = lr + h * 64;
                float4 v = *(const float4*)(B + (size_t)(bn + n) * K + kk + lc);
                Bs[lc + 0][n] = v.x; Bs[lc + 1][n] = v.y;
                Bs[lc + 2][n] = v.z; Bs[lc + 3][n] = v.w;
            }
        } else {
            #pragma unroll
            for (int h = 0; h < 2; h++) {
                int r = brow + h * 8;
                float4 v = *(const float4*)(B + (size_t)(kk + r) * N + bn + bcol);
                *(float4*)&Bs[r][bcol] = v;
            }
        }
        __syncthreads();
        #pragma unroll
        for (int k = 0; k < 16; k++) {
            float4 a0 = *(const float4*)&As[k][ty * 4];
            float4 a1 = *(const float4*)&As[k][ty * 4 + 64];
            float4 b0 = *(const float4*)&Bs[k][tx * 4];
            float4 b1 = *(const float4*)&Bs[k][tx * 4 + 64];
            float ar[8] = {a0.x, a0.y, a0.z, a0.w, a1.x, a1.y, a1.z, a1.w};
            float br[8] = {b0.x, b0.y, b0.z, b0.w, b1.x, b1.y, b1.z, b1.w};
            #pragma unroll
            for (int i = 0; i < 8; i++)
                #pragma unroll
                for (int jj = 0; jj < 8; jj++) acc[i][jj] += ar[i] * br[jj];
        }
        __syncthreads();
    }
    #pragma unroll
    for (int i = 0; i < 8; i++) {
        int row = bm + ((i < 4) ? (ty * 4 + i) : (ty * 4 + 64 + i - 4));
        *(float4*)(C + (size_t)row * N + bn + tx * 4) =
            make_float4(acc[i][0], acc[i][1], acc[i][2], acc[i][3]);
        *(float4*)(C + (size_t)row * N + bn + tx * 4 + 64) =
            make_float4(acc[i][4], acc[i][5], acc[i][6], acc[i][7]);
    }
}

// ---------------- 6) softmax over p per q; uses symmetry of S (reads row q) ----------------
__global__ __launch_bounds__(256) void ral_softmax_kernel(int ksplit) {
    int q = blockIdx.x;
    int p = threadIdx.x;
    __shared__ float red[256];
    float v = 0.f;
    for (int z = 0; z < ksplit; z++) v += g_S[(size_t)z * 65536 + q * 256 + p];
    v = v * 10.f / g_pnorm[p];
    red[p] = v; __syncthreads();
    for (int s = 128; s > 0; s >>= 1) { if (p < s) red[p] = fmaxf(red[p], red[p + s]); __syncthreads(); }
    float mx = red[0]; __syncthreads();
    float e = __expf(v - mx);
    red[p] = e; __syncthreads();
    for (int s = 128; s > 0; s >>= 1) { if (p < s) red[p] += red[p + s]; __syncthreads(); }
    float inv = 1.f / red[0];
    g_attnT[q * 256 + p] = e * inv;   // [q][p], coalesced
}

// ---------------- 7) gather bg into (16 taps x 512 ch) x 256 patch matrix ----------------
__global__ __launch_bounds__(256) void bgbig_kernel() {
    int row = blockIdx.x;            // combo*512 + c
    int combo = row >> 9;
    int c = row & 511;
    int ki = combo >> 2, kj = combo & 3;
    int p = threadIdx.x;
    int py = p >> 4, px = p & 15;
    int r = 2 * py + ki - 1, col = 2 * px + kj - 1;
    float v = 0.f;
    if ((unsigned)r < 32u && (unsigned)col < 32u) v = g_outres[c * 1024 + r * 32 + col];
    g_bgbig[(size_t)row * 256 + p] = v;
}

// ---------------- 9) scatter deconv taps (T'[q][row]) -> out_32 pixel-major ----------------
__global__ __launch_bounds__(512) void ral_out_kernel() {
    int pix = blockIdx.x;
    int ho = pix >> 5, wo = pix & 31;
    int c = threadIdx.x;
    float acc = 0.f;
    for (int ki = (ho + 1) & 1; ki < 4; ki += 2) {
        int qy = (ho + 1 - ki) >> 1;
        if ((unsigned)qy >= 16u) continue;
        for (int kj = (wo + 1) & 1; kj < 4; kj += 2) {
            int qx = (wo + 1 - kj) >> 1;
            if ((unsigned)qx >= 16u) continue;
            int q = qy * 16 + qx;
            acc += g_T[(size_t)q * 8192 + (ki * 4 + kj) * 512 + c];
        }
    }
    g_out32T[(size_t)pix * 512 + c] = acc * 0.25f;
}

// ---------------- sum 4 split-K partials (gaussian) ----------------
__global__ __launch_bounds__(256) void reduce4_kernel(const float* __restrict__ in,
                                                      float* __restrict__ out, int n) {
    int i = blockIdx.x * 256 + threadIdx.x;
    out[i] = in[i] + in[n + i] + in[2 * n + i] + in[3 * n + i];
}

// ---------------- 11) CSA: per-position 3x3 patch softmax ----------------
__global__ __launch_bounds__(512) void csa_kernel() {
    int pos = blockIdx.x;
    int y = pos >> 5, x = pos & 31;
    int c = threadIdx.x;
    __shared__ float s_sum[16 * 9];
    __shared__ float s_a[9];
    float center = g_out32T[(size_t)pos * 512 + c];
    float sc = 1.f / (1.f + __expf(-center));
    float nb[9], pr[9];
    #pragma unroll
    for (int ij = 0; ij < 9; ij++) {
        int di = ij / 3 - 1, dj = ij % 3 - 1;
        int yy = y + di, xx = x + dj;
        bool ok = (unsigned)yy < 32u && (unsigned)xx < 32u;
        float v = ok ? g_out32T[(size_t)(yy * 32 + xx) * 512 + c] : 0.f;
        nb[ij] = v;
        float sn = ok ? 1.f / (1.f + __expf(-v)) : 0.f;
        pr[ij] = sc * sn;
    }
    #pragma unroll
    for (int ij = 0; ij < 9; ij++)
        #pragma unroll
        for (int o = 16; o > 0; o >>= 1) pr[ij] += __shfl_down_sync(0xFFFFFFFFu, pr[ij], o);
    int w = c >> 5, l = c & 31;
    if (l == 0) {
        #pragma unroll
        for (int ij = 0; ij < 9; ij++) s_sum[w * 9 + ij] = pr[ij];
    }
    __syncthreads();
    if (c < 9) {
        float t = 0.f;
        for (int w2 = 0; w2 < 16; w2++) t += s_sum[w2 * 9 + c];
        s_a[c] = t * (1.f / 512.f);
    }
    __syncthreads();
    if (c == 0) {
        float mx = s_a[0];
        for (int ij = 1; ij < 9; ij++) mx = fmaxf(mx, s_a[ij]);
        float sum = 0.f; float e[9];
        for (int ij = 0; ij < 9; ij++) { e[ij] = __expf(s_a[ij] - mx); sum += e[ij]; }
        float invs = 1.f / sum;
        for (int ij = 0; ij < 9; ij++) s_a[ij] = e[ij] * invs;
    }
    __syncthreads();
    float out = 0.f;
    #pragma unroll
    for (int ij = 0; ij < 9; ij++) out += s_a[ij] * nb[ij];
    g_z[512 * 1024 + (size_t)pos * 512 + c] = out;
}

// ------------- instance norm + leaky relu; sums npart split-K slices; optional concat copy ----
__global__ __launch_bounds__(256) void norm_leaky_kernel(
    const float* __restrict__ in, int npart, float* __restrict__ outA,
    const float* __restrict__ cpsrc, float* __restrict__ outB) {
    __shared__ float s_red[64];
    int c = blockIdx.x, tid = threadIdx.x;
    float v[4]; float s = 0.f, s2 = 0.f;
    #pragma unroll
    for (int q = 0; q < 4; q++) {
        int idx = c * 1024 + tid + q * 256;
        float acc = in[idx];
        for (int z = 1; z < npart; z++) acc += in[(size_t)z * 512 * 1024 + idx];
        v[q] = acc;
        s += acc; s2 += acc * acc;
    }
    blockReduce2(s, s2, s_red);
    float mu = s * (1.f / 1024.f);
    float inv = rsqrtf(s2 * (1.f / 1024.f) - mu * mu + 1e-5f);
    #pragma unroll
    for (int q = 0; q < 4; q++) {
        float f = (v[q] - mu) * inv;
        outA[c * 1024 + tid + q * 256] = f >= 0.f ? f : 0.2f * f;
    }
    if (cpsrc != nullptr) {
        #pragma unroll
        for (int q = 0; q < 4; q++)
            outB[c * 1024 + tid + q * 256] = cpsrc[c * 1024 + tid + q * 256];
    }
}

// ---------------- host ----------------
extern "C" void kernel_launch(void* const* d_in, const int* in_sizes, int n_in,
                              void* d_out, int out_size) {
    const float* x     = (const float*)d_in[0];
    const float* gus   = (const float*)d_in[1];
    const float* w_sk3 = (const float*)d_in[2];
    const float* b_sk3 = (const float*)d_in[3];
    const float* w_sk5 = (const float*)d_in[4];
    const float* b_sk5 = (const float*)d_in[5];
    const float* w_sk7 = (const float*)d_in[6];
    const float* b_sk7 = (const float*)d_in[7];
    const float* w_fc  = (const float*)d_in[8];
    const float* b_fc  = (const float*)d_in[9];
    const float* w_fc0 = (const float*)d_in[10];
    const float* b_fc0 = (const float*)d_in[11];
    const float* w_fc1 = (const float*)d_in[12];
    const float* b_fc1 = (const float*)d_in[13];
    const float* w_fc2 = (const float*)d_in[14];
    const float* b_fc2 = (const float*)d_in[15];
    const float* w_down = (const float*)d_in[16];
    const float* w_fuse = (const float*)d_in[17];

    float *P, *S, *attnT, *bgbig, *T, *out32T, *z, *d1, *z2, *outres;
    cudaGetSymbolAddress((void**)&P, g_P);
    cudaGetSymbolAddress((void**)&S, g_S);
    cudaGetSymbolAddress((void**)&attnT, g_attnT);
    cudaGetSymbolAddress((void**)&bgbig, g_bgbig);
    cudaGetSymbolAddress((void**)&T, g_T);
    cudaGetSymbolAddress((void**)&out32T, g_out32T);
    cudaGetSymbolAddress((void**)&z, g_z);
    cudaGetSymbolAddress((void**)&d1, g_d1);
    cudaGetSymbolAddress((void**)&z2, g_z2);
    cudaGetSymbolAddress((void**)&outres, g_outres);

    // SKConv branches (conv + IN + relu + pixel sums)
    sk_conv_kernel<3><<<512, 256>>>(x, w_sk3, b_sk3, 0);
    sk_conv_kernel<5><<<512, 256>>>(x, w_sk5, b_sk5, 1);
    sk_conv_kernel<7><<<512, 256>>>(x, w_sk7, b_sk7, 2);
    // channel attention
    att_kernel<<<1, 512>>>(w_fc, b_fc, w_fc0, b_fc0, w_fc1, b_fc1, w_fc2, b_fc2);
    // weighted combine -> out_res, fg_small
    combine_kernel<<<512, 256>>>();
    // RAL
    patch_kernel<<<256, 256>>>();
    gemm128<true><<<dim3(2, 2, 32), 256>>>(P, P, S, 256, 256, 4608, 32);     // D = P P^T
    ral_softmax_kernel<<<256, 256>>>(32);
    bgbig_kernel<<<8192, 256>>>();
    gemm128<true><<<dim3(64, 2, 1), 256>>>(attnT, bgbig, T, 256, 8192, 256, 1); // T' = attnT bgbig^T
    ral_out_kernel<<<1024, 512>>>();
    // gaussian einsum -> first half of z (split-K 4 into T scratch, then reduce)
    gemm128<false><<<dim3(4, 8, 4), 256>>>(gus, out32T, T, 1024, 512, 1024, 4);
    reduce4_kernel<<<2048, 256>>>(T, z, 1024 * 512);
    // CSA -> second half of z
    csa_kernel<<<1024, 512>>>();
    // down 1x1 conv (split-K 4) + IN + leaky, concat out_res
    gemm128<false><<<dim3(8, 4, 4), 256>>>(w_down, z, d1, 512, 1024, 1024, 4);
    norm_leaky_kernel<<<512, 256>>>(d1, 4, z2, outres, z2 + 512 * 1024);
    // fuse 1x1 conv (split-K 4) + IN + leaky -> output
    gemm128<false><<<dim3(8, 4, 4), 256>>>(w_fuse, z2, d1, 512, 1024, 1024, 4);
    norm_leaky_kernel<<<512, 256>>>(d1, 4, (float*)d_out, nullptr, nullptr);
}

// round 3
// speedup vs baseline: 1.5444x; 1.2527x over previous
#include <cuda_runtime.h>
#include <cstddef>

// ---------------- scratch (static __device__, no allocs) ----------------
__device__ float g_feas[3 * 512 * 1024];
__device__ float g_bsum[3 * 512];
__device__ float g_fz[32];
__device__ float g_outres[512 * 1024];
__device__ float g_fgs[512 * 256];
__device__ float g_P[256 * 4608];
__device__ float g_pnorm[256];
__device__ float g_S[32 * 256 * 256];     // split-K partials of score (symmetric)
__device__ float g_attnT[256 * 256];      // attn transposed: [q][p]
__device__ float g_T[256 * 8192];         // T'[q][row]; reused for gaussian partials
__device__ float g_out32T[1024 * 512];    // post-RAL out_32, pixel-major
__device__ float g_z[1024 * 1024];        // concat(gus_out, out_csa)
__device__ float g_d1[4 * 512 * 1024];    // split-K partials of down/fuse
__device__ float g_z2[1024 * 1024];       // concat(leaky(norm(down)), out_res)

// ---------------- helpers ----------------
__device__ __forceinline__ void blockReduce2(float& s, float& s2, float* sm) {
    __syncthreads();
    int tid = threadIdx.x;
    #pragma unroll
    for (int o = 16; o > 0; o >>= 1) {
        s  += __shfl_down_sync(0xFFFFFFFFu, s, o);
        s2 += __shfl_down_sync(0xFFFFFFFFu, s2, o);
    }
    int w = tid >> 5, l = tid & 31;
    int nw = blockDim.x >> 5;
    if (l == 0) { sm[w] = s; sm[32 + w] = s2; }
    __syncthreads();
    if (tid < 32) {
        s  = (tid < nw) ? sm[tid] : 0.f;
        s2 = (tid < nw) ? sm[32 + tid] : 0.f;
        #pragma unroll
        for (int o = 16; o > 0; o >>= 1) {
            s  += __shfl_down_sync(0xFFFFFFFFu, s, o);
            s2 += __shfl_down_sync(0xFFFFFFFFu, s2, o);
        }
        if (tid == 0) { sm[0] = s; sm[32] = s2; }
    }
    __syncthreads();
    s = sm[0]; s2 = sm[32];
}

// ---------------- 1) SK grouped conv + instance norm + relu (all 3 branches) ----------------
template <int KS>
__device__ __forceinline__ void sk_conv_impl(
    const float* __restrict__ x, const float* __restrict__ w,
    const float* __restrict__ bias, int branch,
    float* s_ch, float* s_w, float* s_red) {
    constexpr int PAD = KS / 2;
    int oc = blockIdx.x;
    int tid = threadIdx.x;
    const float* xin = x + (size_t)(oc >> 4) * 16 * 1024;
    const float* wo = w + (size_t)oc * 16 * KS * KS;
    for (int i = tid; i < 16 * KS * KS; i += 256) s_w[i] = wo[i];

    float acc[4] = {0.f, 0.f, 0.f, 0.f};
    for (int ic = 0; ic < 16; ic++) {
        __syncthreads();
        for (int i = tid; i < 1024; i += 256) s_ch[i] = xin[ic * 1024 + i];
        __syncthreads();
        const float* wi = &s_w[ic * KS * KS];
        #pragma unroll
        for (int q = 0; q < 4; q++) {
            int p = tid + q * 256;
            int y = p >> 5, xx = p & 31;
            float a = acc[q];
            #pragma unroll
            for (int ky = 0; ky < KS; ky++) {
                int iy = y + ky - PAD;
                if ((unsigned)iy < 32u) {
                    #pragma unroll
                    for (int kx = 0; kx < KS; kx++) {
                        int ix = xx + kx - PAD;
                        if ((unsigned)ix < 32u)
                            a += s_ch[iy * 32 + ix] * wi[ky * KS + kx];
                    }
                }
            }
            acc[q] = a;
        }
    }
    float b = bias[oc];
    float s = 0.f, s2 = 0.f;
    #pragma unroll
    for (int q = 0; q < 4; q++) { acc[q] += b; s += acc[q]; s2 += acc[q] * acc[q]; }
    blockReduce2(s, s2, s_red);
    float mu = s * (1.f / 1024.f);
    float var = s2 * (1.f / 1024.f) - mu * mu;
    float inv = rsqrtf(var + 1e-5f);
    float rs = 0.f;
    float* fo = &g_feas[(size_t)branch * 512 * 1024 + (size_t)oc * 1024];
    #pragma unroll
    for (int q = 0; q < 4; q++) {
        float r = (acc[q] - mu) * inv;
        r = fmaxf(r, 0.f);
        fo[tid + q * 256] = r;
        rs += r;
    }
    float dummy = 0.f;
    blockReduce2(rs, dummy, s_red);
    if (tid == 0) g_bsum[branch * 512 + oc] = rs;
}

__global__ __launch_bounds__(256) void sk_conv_all(
    const float* __restrict__ x,
    const float* __restrict__ w3, const float* __restrict__ b3,
    const float* __restrict__ w5, const float* __restrict__ b5,
    const float* __restrict__ w7, const float* __restrict__ b7) {
    __shared__ float s_ch[1024];
    __shared__ float s_w[16 * 49];
    __shared__ float s_red[64];
    int br = blockIdx.y;
    if (br == 0)      sk_conv_impl<3>(x, w3, b3, 0, s_ch, s_w, s_red);
    else if (br == 1) sk_conv_impl<5>(x, w5, b5, 1, s_ch, s_w, s_red);
    else              sk_conv_impl<7>(x, w7, b7, 2, s_ch, s_w, s_red);
}

// ---------------- 2) FC1: fz[j] = fea_s . w_fc[j] + b_fc[j], one block per j ----------------
__global__ __launch_bounds__(256) void fz_kernel(
    const float* __restrict__ w_fc, const float* __restrict__ b_fc) {
    __shared__ float s_red[64];
    int j = blockIdx.x, tid = threadIdx.x;
    float s = 0.f;
    for (int c = tid; c < 512; c += 256) {
        float fs = (g_bsum[c] + g_bsum[512 + c] + g_bsum[1024 + c]) * (1.f / 1024.f);
        s += fs * w_fc[j * 512 + c];
    }
    float dummy = 0.f;
    blockReduce2(s, dummy, s_red);
    if (tid == 0) g_fz[j] = s + b_fc[j];
}

// ------- 3) per-channel branch attention + combine -> out_res; 2x2 avg pool -> fg_small ------
__global__ __launch_bounds__(256) void combine_kernel(
    const float* __restrict__ w0, const float* __restrict__ b0,
    const float* __restrict__ w1, const float* __restrict__ b1,
    const float* __restrict__ w2, const float* __restrict__ b2) {
    int c = blockIdx.x, tid = threadIdx.x;
    __shared__ float s_fz[32];
    __shared__ float s_a[3];
    __shared__ float s_o[1024];
    if (tid < 32) s_fz[tid] = g_fz[tid];
    __syncthreads();
    int w = tid >> 5, l = tid & 31;
    if (w < 3) {
        const float* wt = (w == 0) ? w0 : (w == 1) ? w1 : w2;
        const float* bt = (w == 0) ? b0 : (w == 1) ? b1 : b2;
        float v = s_fz[l] * wt[c * 32 + l];
        #pragma unroll
        for (int o = 16; o > 0; o >>= 1) v += __shfl_down_sync(0xFFFFFFFFu, v, o);
        if (l == 0) s_a[w] = v + bt[c];
    }
    __syncthreads();
    float A0 = s_a[0], A1 = s_a[1], A2 = s_a[2];
    float mx = fmaxf(A0, fmaxf(A1, A2));
    float e0 = __expf(A0 - mx), e1 = __expf(A1 - mx), e2 = __expf(A2 - mx);
    float inv = 1.f / (e0 + e1 + e2);
    float a0 = e0 * inv, a1 = e1 * inv, a2 = e2 * inv;

    for (int i = tid; i < 1024; i += 256) {
        float v = a0 * g_feas[(size_t)c * 1024 + i]
                + a1 * g_feas[512 * 1024 + (size_t)c * 1024 + i]
                + a2 * g_feas[2 * 512 * 1024 + (size_t)c * 1024 + i];
        g_outres[c * 1024 + i] = v;
        s_o[i] = v;
    }
    __syncthreads();
    if (tid < 256) {
        int py = tid >> 4, px = tid & 15;
        float p = 0.25f * (s_o[(2 * py) * 32 + 2 * px] + s_o[(2 * py) * 32 + 2 * px + 1] +
                           s_o[(2 * py + 1) * 32 + 2 * px] + s_o[(2 * py + 1) * 32 + 2 * px + 1]);
        g_fgs[c * 256 + tid] = p;
    }
}

// ---------------- 4) build patch matrix P (256x4608) + norms ----------------
__global__ __launch_bounds__(256) void patch_kernel() {
    __shared__ float s_red[64];
    int p = blockIdx.x;
    int py = p >> 4, px = p & 15;
    int tid = threadIdx.x;
    float ss = 0.f;
    for (int k = tid; k < 4608; k += 256) {
        int c = k / 9, ij = k - c * 9;
        int di = ij / 3, dj = ij - di * 3;
        int y = py + di - 1, x = px + dj - 1;
        float v = 0.f;
        if ((unsigned)y < 16u && (unsigned)x < 16u) v = g_fgs[c * 256 + y * 16 + x];
        g_P[(size_t)p * 4608 + k] = v;
        ss += v * v;
    }
    float dummy = 0.f;
    blockReduce2(ss, dummy, s_red);
    if (tid == 0) g_pnorm[p] = fmaxf(sqrtf(ss), 1e-4f);
}

// ---- 128x128-tile SGEMM, 8x8/thread, software-pipelined.
//      BT=false: C=A(MxK)*B(KxN);  BT=true: C=A(MxK)*B(NxK)^T.
//      GATHER: B[n][k] gathered on-the-fly from outres (deconv bg taps). ----
template <bool BT, bool GATHER>
__global__ __launch_bounds__(256) void gemm128(
    const float* __restrict__ A, const float* __restrict__ B, float* __restrict__ C,
    int M, int N, int K, int ksplit) {
    __shared__ float As[16][132];
    __shared__ float Bs[16][132];
    int tid = threadIdx.x;
    int bm = blockIdx.y * 128, bn = blockIdx.x * 128;
    int kchunk = K / ksplit, k0 = blockIdx.z * kchunk, kend = k0 + kchunk;
    C += (size_t)blockIdx.z * M * N;
    int lr = tid >> 2, lc = (tid & 3) * 4;
    int brow = tid >> 5, bcol = (tid & 31) * 4;
    int tx = tid & 15, ty = tid >> 4;

    float4 pa[2], pb[2];
    auto loadA = [&](int kk) {
        #pragma unroll
        for (int h = 0; h < 2; h++)
            pa[h] = *(const float4*)(A + (size_t)(bm + lr + h * 64) * K + kk + lc);
    };
    auto loadB = [&](int kk) {
        if (GATHER) {
            #pragma unroll
            for (int h = 0; h < 2; h++) {
                int n = bn + lr + h * 64;
                int combo = n >> 9, c = n & 511;
                int ki = combo >> 2, kj = combo & 3;
                float v[4];
                #pragma unroll
                for (int t = 0; t < 4; t++) {
                    int p = kk + lc + t;
                    int py = p >> 4, px = p & 15;
                    int r = 2 * py + ki - 1, col = 2 * px + kj - 1;
                    v[t] = ((unsigned)r < 32u && (unsigned)col < 32u)
                         ? B[c * 1024 + r * 32 + col] : 0.f;
                }
                pb[h] = make_float4(v[0], v[1], v[2], v[3]);
            }
        } else if (BT) {
            #pragma unroll
            for (int h = 0; h < 2; h++)
                pb[h] = *(const float4*)(B + (size_t)(bn + lr + h * 64) * K + kk + lc);
        } else {
            #pragma unroll
            for (int h = 0; h < 2; h++)
                pb[h] = *(const float4*)(B + (size_t)(kk + brow + h * 8) * N + bn + bcol);
        }
    };
    auto storeTiles = [&]() {
        #pragma unroll
        for (int h = 0; h < 2; h++) {
            int r = lr + h * 64;
            As[lc + 0][r] = pa[h].x; As[lc + 1][r] = pa[h].y;
            As[lc + 2][r] = pa[h].z; As[lc + 3][r] = pa[h].w;
        }
        if (BT || GATHER) {
            #pragma unroll
            for (int h = 0; h < 2; h++) {
                int n = lr + h * 64;
                Bs[lc + 0][n] = pb[h].x; Bs[lc + 1][n] = pb[h].y;
                Bs[lc + 2][n] = pb[h].z; Bs[lc + 3][n] = pb[h].w;
            }
        } else {
            #pragma unroll
            for (int h = 0; h < 2; h++)
                *(float4*)&Bs[brow + h * 8][bcol] = pb[h];
        }
    };

    float acc[8][8] = {};
    loadA(k0); loadB(k0);
    for (int kk = k0; kk < kend; kk += 16) {
        storeTiles();
        __syncthreads();
        if (kk + 16 < kend) { loadA(kk + 16); loadB(kk + 16); }
        #pragma unroll
        for (int k = 0; k < 16; k++) {
            float4 a0 = *(const float4*)&As[k][ty * 4];
            float4 a1 = *(const float4*)&As[k][ty * 4 + 64];
            float4 b0 = *(const float4*)&Bs[k][tx * 4];
            float4 b1 = *(const float4*)&Bs[k][tx * 4 + 64];
            float ar[8] = {a0.x, a0.y, a0.z, a0.w, a1.x, a1.y, a1.z, a1.w};
            float br[8] = {b0.x, b0.y, b0.z, b0.w, b1.x, b1.y, b1.z, b1.w};
            #pragma unroll
            for (int i = 0; i < 8; i++)
                #pragma unroll
                for (int jj = 0; jj < 8; jj++) acc[i][jj] += ar[i] * br[jj];
        }
        __syncthreads();
    }
    #pragma unroll
    for (int i = 0; i < 8; i++) {
        int row = bm + ((i < 4) ? (ty * 4 + i) : (ty * 4 + 64 + i - 4));
        *(float4*)(C + (size_t)row * N + bn + tx * 4) =
            make_float4(acc[i][0], acc[i][1], acc[i][2], acc[i][3]);
        *(float4*)(C + (size_t)row * N + bn + tx * 4 + 64) =
            make_float4(acc[i][4], acc[i][5], acc[i][6], acc[i][7]);
    }
}

// ---------------- 6) softmax over p per q; uses symmetry of S (reads row q) ----------------
__global__ __launch_bounds__(256) void ral_softmax_kernel(int ksplit) {
    int q = blockIdx.x;
    int p = threadIdx.x;
    __shared__ float red[256];
    float v = 0.f;
    for (int z = 0; z < ksplit; z++) v += g_S[(size_t)z * 65536 + q * 256 + p];
    v = v * 10.f / g_pnorm[p];
    red[p] = v; __syncthreads();
    for (int s = 128; s > 0; s >>= 1) { if (p < s) red[p] = fmaxf(red[p], red[p + s]); __syncthreads(); }
    float mx = red[0]; __syncthreads();
    float e = __expf(v - mx);
    red[p] = e; __syncthreads();
    for (int s = 128; s > 0; s >>= 1) { if (p < s) red[p] += red[p + s]; __syncthreads(); }
    float inv = 1.f / red[0];
    g_attnT[q * 256 + p] = e * inv;   // [q][p], coalesced
}

// ---------------- 9) scatter deconv taps (T'[q][row]) -> out_32 pixel-major ----------------
__global__ __launch_bounds__(512) void ral_out_kernel() {
    int pix = blockIdx.x;
    int ho = pix >> 5, wo = pix & 31;
    int c = threadIdx.x;
    float acc = 0.f;
    for (int ki = (ho + 1) & 1; ki < 4; ki += 2) {
        int qy = (ho + 1 - ki) >> 1;
        if ((unsigned)qy >= 16u) continue;
        for (int kj = (wo + 1) & 1; kj < 4; kj += 2) {
            int qx = (wo + 1 - kj) >> 1;
            if ((unsigned)qx >= 16u) continue;
            int q = qy * 16 + qx;
            acc += g_T[(size_t)q * 8192 + (ki * 4 + kj) * 512 + c];
        }
    }
    g_out32T[(size_t)pix * 512 + c] = acc * 0.25f;
}

// ---------------- sum 4 split-K partials (gaussian) ----------------
__global__ __launch_bounds__(256) void reduce4_kernel(const float* __restrict__ in,
                                                      float* __restrict__ out, int n) {
    int i = blockIdx.x * 256 + threadIdx.x;
    out[i] = in[i] + in[n + i] + in[2 * n + i] + in[3 * n + i];
}

// ---------------- 11) CSA: per-position 3x3 patch softmax ----------------
__global__ __launch_bounds__(512) void csa_kernel() {
    int pos = blockIdx.x;
    int y = pos >> 5, x = pos & 31;
    int c = threadIdx.x;
    __shared__ float s_sum[16 * 9];
    __shared__ float s_a[9];
    float center = g_out32T[(size_t)pos * 512 + c];
    float sc = 1.f / (1.f + __expf(-center));
    float nb[9], pr[9];
    #pragma unroll
    for (int ij = 0; ij < 9; ij++) {
        int di = ij / 3 - 1, dj = ij % 3 - 1;
        int yy = y + di, xx = x + dj;
        bool ok = (unsigned)yy < 32u && (unsigned)xx < 32u;
        float v = ok ? g_out32T[(size_t)(yy * 32 + xx) * 512 + c] : 0.f;
        nb[ij] = v;
        float sn = ok ? 1.f / (1.f + __expf(-v)) : 0.f;
        pr[ij] = sc * sn;
    }
    #pragma unroll
    for (int ij = 0; ij < 9; ij++)
        #pragma unroll
        for (int o = 16; o > 0; o >>= 1) pr[ij] += __shfl_down_sync(0xFFFFFFFFu, pr[ij], o);
    int w = c >> 5, l = c & 31;
    if (l == 0) {
        #pragma unroll
        for (int ij = 0; ij < 9; ij++) s_sum[w * 9 + ij] = pr[ij];
    }
    __syncthreads();
    if (c < 9) {
        float t = 0.f;
        for (int w2 = 0; w2 < 16; w2++) t += s_sum[w2 * 9 + c];
        s_a[c] = t * (1.f / 512.f);
    }
    __syncthreads();
    if (c == 0) {
        float mx = s_a[0];
        for (int ij = 1; ij < 9; ij++) mx = fmaxf(mx, s_a[ij]);
        float sum = 0.f; float e[9];
        for (int ij = 0; ij < 9; ij++) { e[ij] = __expf(s_a[ij] - mx); sum += e[ij]; }
        float invs = 1.f / sum;
        for (int ij = 0; ij < 9; ij++) s_a[ij] = e[ij] * invs;
    }
    __syncthreads();
    float out = 0.f;
    #pragma unroll
    for (int ij = 0; ij < 9; ij++) out += s_a[ij] * nb[ij];
    g_z[512 * 1024 + (size_t)pos * 512 + c] = out;
}

// ------------- instance norm + leaky relu; sums npart split-K slices; optional concat copy ----
__global__ __launch_bounds__(256) void norm_leaky_kernel(
    const float* __restrict__ in, int npart, float* __restrict__ outA,
    const float* __restrict__ cpsrc, float* __restrict__ outB) {
    __shared__ float s_red[64];
    int c = blockIdx.x, tid = threadIdx.x;
    float v[4]; float s = 0.f, s2 = 0.f;
    #pragma unroll
    for (int q = 0; q < 4; q++) {
        int idx = c * 1024 + tid + q * 256;
        float acc = in[idx];
        for (int z = 1; z < npart; z++) acc += in[(size_t)z * 512 * 1024 + idx];
        v[q] = acc;
        s += acc; s2 += acc * acc;
    }
    blockReduce2(s, s2, s_red);
    float mu = s * (1.f / 1024.f);
    float inv = rsqrtf(s2 * (1.f / 1024.f) - mu * mu + 1e-5f);
    #pragma unroll
    for (int q = 0; q < 4; q++) {
        float f = (v[q] - mu) * inv;
        outA[c * 1024 + tid + q * 256] = f >= 0.f ? f : 0.2f * f;
    }
    if (cpsrc != nullptr) {
        #pragma unroll
        for (int q = 0; q < 4; q++)
            outB[c * 1024 + tid + q * 256] = cpsrc[c * 1024 + tid + q * 256];
    }
}

// ---------------- host ----------------
extern "C" void kernel_launch(void* const* d_in, const int* in_sizes, int n_in,
                              void* d_out, int out_size) {
    const float* x     = (const float*)d_in[0];
    const float* gus   = (const float*)d_in[1];
    const float* w_sk3 = (const float*)d_in[2];
    const float* b_sk3 = (const float*)d_in[3];
    const float* w_sk5 = (const float*)d_in[4];
    const float* b_sk5 = (const float*)d_in[5];
    const float* w_sk7 = (const float*)d_in[6];
    const float* b_sk7 = (const float*)d_in[7];
    const float* w_fc  = (const float*)d_in[8];
    const float* b_fc  = (const float*)d_in[9];
    const float* w_fc0 = (const float*)d_in[10];
    const float* b_fc0 = (const float*)d_in[11];
    const float* w_fc1 = (const float*)d_in[12];
    const float* b_fc1 = (const float*)d_in[13];
    const float* w_fc2 = (const float*)d_in[14];
    const float* b_fc2 = (const float*)d_in[15];
    const float* w_down = (const float*)d_in[16];
    const float* w_fuse = (const float*)d_in[17];

    float *P, *S, *attnT, *T, *out32T, *z, *d1, *z2, *outres;
    cudaGetSymbolAddress((void**)&P, g_P);
    cudaGetSymbolAddress((void**)&S, g_S);
    cudaGetSymbolAddress((void**)&attnT, g_attnT);
    cudaGetSymbolAddress((void**)&T, g_T);
    cudaGetSymbolAddress((void**)&out32T, g_out32T);
    cudaGetSymbolAddress((void**)&z, g_z);
    cudaGetSymbolAddress((void**)&d1, g_d1);
    cudaGetSymbolAddress((void**)&z2, g_z2);
    cudaGetSymbolAddress((void**)&outres, g_outres);

    // SKConv all branches (conv + IN + relu + pixel sums)
    sk_conv_all<<<dim3(512, 3), 256>>>(x, w_sk3, b_sk3, w_sk5, b_sk5, w_sk7, b_sk7);
    // channel attention FC1 (parallel across 32 blocks)
    fz_kernel<<<32, 256>>>(w_fc, b_fc);
    // per-channel attention + combine -> out_res, fg_small
    combine_kernel<<<512, 256>>>(w_fc0, b_fc0, w_fc1, b_fc1, w_fc2, b_fc2);
    // RAL
    patch_kernel<<<256, 256>>>();
    gemm128<true, false><<<dim3(2, 2, 32), 256>>>(P, P, S, 256, 256, 4608, 32);      // D = P P^T
    ral_softmax_kernel<<<256, 256>>>(32);
    gemm128<true, true><<<dim3(64, 2, 1), 256>>>(attnT, outres, T, 256, 8192, 256, 1); // T' = attnT * gather(bg)^T
    ral_out_kernel<<<1024, 512>>>();
    // gaussian einsum -> first half of z (split-K 4 into T scratch, then reduce)
    gemm128<false, false><<<dim3(4, 8, 4), 256>>>(gus, out32T, T, 1024, 512, 1024, 4);
    reduce4_kernel<<<2048, 256>>>(T, z, 1024 * 512);
    // CSA -> second half of z
    csa_kernel<<<1024, 512>>>();
    // down 1x1 conv (split-K 4) + IN + leaky, concat out_res
    gemm128<false, false><<<dim3(8, 4, 4), 256>>>(w_down, z, d1, 512, 1024, 1024, 4);
    norm_leaky_kernel<<<512, 256>>>(d1, 4, z2, outres, z2 + 512 * 1024);
    // fuse 1x1 conv (split-K 4) + IN + leaky -> output
    gemm128<false, false><<<dim3(8, 4, 4), 256>>>(w_fuse, z2, d1, 512, 1024, 1024, 4);
    norm_leaky_kernel<<<512, 256>>>(d1, 4, (float*)d_out, nullptr, nullptr);
}

// round 4
// speedup vs baseline: 1.8535x; 1.2001x over previous
#include <cuda_runtime.h>
#include <cstddef>

// ---------------- scratch (static __device__, no allocs) ----------------
__device__ float g_feas[3 * 512 * 1024];
__device__ float g_bsum[3 * 512];
__device__ float g_fz[32];
__device__ float g_outres[512 * 1024];
__device__ float g_fgsT[256 * 512];       // fg_small, pixel-major [pos][c]
__device__ float g_pnorm[256];
__device__ float g_S[4 * 256 * 256];      // split-K partials of R = F^T F
__device__ float g_attnT[256 * 256];      // attn transposed: [q][p]
__device__ float g_T[256 * 8192];         // T'[q][row]; reused for gaussian partials
__device__ float g_out32T[1024 * 512];    // post-RAL out_32, pixel-major
__device__ float g_z[1024 * 1024];        // concat(gus_out, out_csa)
__device__ float g_d1[4 * 512 * 1024];    // split-K partials of down/fuse
__device__ float g_z2[1024 * 1024];       // concat(leaky(norm(down)), out_res)

// ---------------- helpers ----------------
__device__ __forceinline__ void blockReduce2(float& s, float& s2, float* sm) {
    __syncthreads();
    int tid = threadIdx.x;
    #pragma unroll
    for (int o = 16; o > 0; o >>= 1) {
        s  += __shfl_down_sync(0xFFFFFFFFu, s, o);
        s2 += __shfl_down_sync(0xFFFFFFFFu, s2, o);
    }
    int w = tid >> 5, l = tid & 31;
    int nw = blockDim.x >> 5;
    if (l == 0) { sm[w] = s; sm[32 + w] = s2; }
    __syncthreads();
    if (tid < 32) {
        s  = (tid < nw) ? sm[tid] : 0.f;
        s2 = (tid < nw) ? sm[32 + tid] : 0.f;
        #pragma unroll
        for (int o = 16; o > 0; o >>= 1) {
            s  += __shfl_down_sync(0xFFFFFFFFu, s, o);
            s2 += __shfl_down_sync(0xFFFFFFFFu, s2, o);
        }
        if (tid == 0) { sm[0] = s; sm[32] = s2; }
    }
    __syncthreads();
    s = sm[0]; s2 = sm[32];
}

// ------- 1) SK grouped conv (zero-padded smem tile, no predicates) + IN + relu -------
template <int KS>
__device__ __forceinline__ void sk_conv_impl(
    const float* __restrict__ x, const float* __restrict__ w,
    const float* __restrict__ bias, int branch,
    float* s_ch, float* s_w, float* s_red) {
    constexpr int PAD = KS / 2;
    constexpr int W = 32 + 2 * PAD;
    int oc = blockIdx.x;
    int tid = threadIdx.x;
    const float* xin = x + (size_t)(oc >> 4) * 16 * 1024;
    const float* wo = w + (size_t)oc * 16 * KS * KS;
    for (int i = tid; i < 16 * KS * KS; i += 256) s_w[i] = wo[i];
    // zero whole tile once; interior is overwritten each ic, border stays 0
    for (int i = tid; i < W * W; i += 256) s_ch[i] = 0.f;

    float acc[4] = {0.f, 0.f, 0.f, 0.f};
    for (int ic = 0; ic < 16; ic++) {
        __syncthreads();
        for (int i = tid; i < 1024; i += 256) {
            int y = i >> 5, xx = i & 31;
            s_ch[(y + PAD) * W + xx + PAD] = xin[ic * 1024 + i];
        }
        __syncthreads();
        const float* wi = &s_w[ic * KS * KS];
        #pragma unroll
        for (int q = 0; q < 4; q++) {
            int p = tid + q * 256;
            int y = p >> 5, xx = p & 31;
            float a = acc[q];
            #pragma unroll
            for (int ky = 0; ky < KS; ky++) {
                const float* row = &s_ch[(y + ky) * W + xx];
                #pragma unroll
                for (int kx = 0; kx < KS; kx++)
                    a += row[kx] * wi[ky * KS + kx];
            }
            acc[q] = a;
        }
    }
    float b = bias[oc];
    float s = 0.f, s2 = 0.f;
    #pragma unroll
    for (int q = 0; q < 4; q++) { acc[q] += b; s += acc[q]; s2 += acc[q] * acc[q]; }
    blockReduce2(s, s2, s_red);
    float mu = s * (1.f / 1024.f);
    float var = s2 * (1.f / 1024.f) - mu * mu;
    float inv = rsqrtf(var + 1e-5f);
    float rs = 0.f;
    float* fo = &g_feas[(size_t)branch * 512 * 1024 + (size_t)oc * 1024];
    #pragma unroll
    for (int q = 0; q < 4; q++) {
        float r = (acc[q] - mu) * inv;
        r = fmaxf(r, 0.f);
        fo[tid + q * 256] = r;
        rs += r;
    }
    float dummy = 0.f;
    blockReduce2(rs, dummy, s_red);
    if (tid == 0) g_bsum[branch * 512 + oc] = rs;
}

__global__ __launch_bounds__(256) void sk_conv_all(
    const float* __restrict__ x,
    const float* __restrict__ w3, const float* __restrict__ b3,
    const float* __restrict__ w5, const float* __restrict__ b5,
    const float* __restrict__ w7, const float* __restrict__ b7) {
    __shared__ float s_ch[38 * 38];
    __shared__ float s_w[16 * 49];
    __shared__ float s_red[64];
    int br = blockIdx.y;
    if (br == 0)      sk_conv_impl<3>(x, w3, b3, 0, s_ch, s_w, s_red);
    else if (br == 1) sk_conv_impl<5>(x, w5, b5, 1, s_ch, s_w, s_red);
    else              sk_conv_impl<7>(x, w7, b7, 2, s_ch, s_w, s_red);
}

// ---------------- 2) FC1: fz[j] = fea_s . w_fc[j] + b_fc[j], one block per j ----------------
__global__ __launch_bounds__(256) void fz_kernel(
    const float* __restrict__ w_fc, const float* __restrict__ b_fc) {
    __shared__ float s_red[64];
    int j = blockIdx.x, tid = threadIdx.x;
    float s = 0.f;
    for (int c = tid; c < 512; c += 256) {
        float fs = (g_bsum[c] + g_bsum[512 + c] + g_bsum[1024 + c]) * (1.f / 1024.f);
        s += fs * w_fc[j * 512 + c];
    }
    float dummy = 0.f;
    blockReduce2(s, dummy, s_red);
    if (tid == 0) g_fz[j] = s + b_fc[j];
}

// ------- 3) per-channel branch attention + combine -> out_res; 2x2 avg pool -> fgsT ------
__global__ __launch_bounds__(256) void combine_kernel(
    const float* __restrict__ w0, const float* __restrict__ b0,
    const float* __restrict__ w1, const float* __restrict__ b1,
    const float* __restrict__ w2, const float* __restrict__ b2) {
    int c = blockIdx.x, tid = threadIdx.x;
    __shared__ float s_fz[32];
    __shared__ float s_a[3];
    __shared__ float s_o[1024];
    if (tid < 32) s_fz[tid] = g_fz[tid];
    __syncthreads();
    int w = tid >> 5, l = tid & 31;
    if (w < 3) {
        const float* wt = (w == 0) ? w0 : (w == 1) ? w1 : w2;
        const float* bt = (w == 0) ? b0 : (w == 1) ? b1 : b2;
        float v = s_fz[l] * wt[c * 32 + l];
        #pragma unroll
        for (int o = 16; o > 0; o >>= 1) v += __shfl_down_sync(0xFFFFFFFFu, v, o);
        if (l == 0) s_a[w] = v + bt[c];
    }
    __syncthreads();
    float A0 = s_a[0], A1 = s_a[1], A2 = s_a[2];
    float mx = fmaxf(A0, fmaxf(A1, A2));
    float e0 = __expf(A0 - mx), e1 = __expf(A1 - mx), e2 = __expf(A2 - mx);
    float inv = 1.f / (e0 + e1 + e2);
    float a0 = e0 * inv, a1 = e1 * inv, a2 = e2 * inv;

    for (int i = tid; i < 1024; i += 256) {
        float v = a0 * g_feas[(size_t)c * 1024 + i]
                + a1 * g_feas[512 * 1024 + (size_t)c * 1024 + i]
                + a2 * g_feas[2 * 512 * 1024 + (size_t)c * 1024 + i];
        g_outres[c * 1024 + i] = v;
        s_o[i] = v;
    }
    __syncthreads();
    int py = tid >> 4, px = tid & 15;
    float p = 0.25f * (s_o[(2 * py) * 32 + 2 * px] + s_o[(2 * py) * 32 + 2 * px + 1] +
                       s_o[(2 * py + 1) * 32 + 2 * px] + s_o[(2 * py + 1) * 32 + 2 * px + 1]);
    g_fgsT[(size_t)tid * 512 + c] = p;   // pixel-major for R GEMM
}

// ---- 128x128-tile SGEMM, 8x8/thread, software-pipelined.
//      BT=false: C=A(MxK)*B(KxN);  BT=true: C=A(MxK)*B(NxK)^T.
//      GATHER: B[n][k] gathered on-the-fly from outres (deconv bg taps). ----
template <bool BT, bool GATHER>
__global__ __launch_bounds__(256) void gemm128(
    const float* __restrict__ A, const float* __restrict__ B, float* __restrict__ C,
    int M, int N, int K, int ksplit) {
    __shared__ float As[16][132];
    __shared__ float Bs[16][132];
    int tid = threadIdx.x;
    int bm = blockIdx.y * 128, bn = blockIdx.x * 128;
    int kchunk = K / ksplit, k0 = blockIdx.z * kchunk, kend = k0 + kchunk;
    C += (size_t)blockIdx.z * M * N;
    int lr = tid >> 2, lc = (tid & 3) * 4;
    int brow = tid >> 5, bcol = (tid & 31) * 4;
    int tx = tid & 15, ty = tid >> 4;

    float4 pa[2], pb[2];
    auto loadA = [&](int kk) {
        #pragma unroll
        for (int h = 0; h < 2; h++)
            pa[h] = *(const float4*)(A + (size_t)(bm + lr + h * 64) * K + kk + lc);
    };
    auto loadB = [&](int kk) {
        if (GATHER) {
            #pragma unroll
            for (int h = 0; h < 2; h++) {
                int n = bn + lr + h * 64;
                int combo = n >> 9, c = n & 511;
                int ki = combo >> 2, kj = combo & 3;
                float v[4];
                #pragma unroll
                for (int t = 0; t < 4; t++) {
                    int p = kk + lc + t;
                    int py = p >> 4, px = p & 15;
                    int r = 2 * py + ki - 1, col = 2 * px + kj - 1;
                    v[t] = ((unsigned)r < 32u && (unsigned)col < 32u)
                         ? B[c * 1024 + r * 32 + col] : 0.f;
                }
                pb[h] = make_float4(v[0], v[1], v[2], v[3]);
            }
        } else if (BT) {
            #pragma unroll
            for (int h = 0; h < 2; h++)
                pb[h] = *(const float4*)(B + (size_t)(bn + lr + h * 64) * K + kk + lc);
        } else {
            #pragma unroll
            for (int h = 0; h < 2; h++)
                pb[h] = *(const float4*)(B + (size_t)(kk + brow + h * 8) * N + bn + bcol);
        }
    };
    auto storeTiles = [&]() {
        #pragma unroll
        for (int h = 0; h < 2; h++) {
            int r = lr + h * 64;
            As[lc + 0][r] = pa[h].x; As[lc + 1][r] = pa[h].y;
            As[lc + 2][r] = pa[h].z; As[lc + 3][r] = pa[h].w;
        }
        if (BT || GATHER) {
            #pragma unroll
            for (int h = 0; h < 2; h++) {
                int n = lr + h * 64;
                Bs[lc + 0][n] = pb[h].x; Bs[lc + 1][n] = pb[h].y;
                Bs[lc + 2][n] = pb[h].z; Bs[lc + 3][n] = pb[h].w;
            }
        } else {
            #pragma unroll
            for (int h = 0; h < 2; h++)
                *(float4*)&Bs[brow + h * 8][bcol] = pb[h];
        }
    };

    float acc[8][8] = {};
    loadA(k0); loadB(k0);
    for (int kk = k0; kk < kend; kk += 16) {
        storeTiles();
        __syncthreads();
        if (kk + 16 < kend) { loadA(kk + 16); loadB(kk + 16); }
        #pragma unroll
        for (int k = 0; k < 16; k++) {
            float4 a0 = *(const float4*)&As[k][ty * 4];
            float4 a1 = *(const float4*)&As[k][ty * 4 + 64];
            float4 b0 = *(const float4*)&Bs[k][tx * 4];
            float4 b1 = *(const float4*)&Bs[k][tx * 4 + 64];
            float ar[8] = {a0.x, a0.y, a0.z, a0.w, a1.x, a1.y, a1.z, a1.w};
            float br[8] = {b0.x, b0.y, b0.z, b0.w, b1.x, b1.y, b1.z, b1.w};
            #pragma unroll
            for (int i = 0; i < 8; i++)
                #pragma unroll
                for (int jj = 0; jj < 8; jj++) acc[i][jj] += ar[i] * br[jj];
        }
        __syncthreads();
    }
    #pragma unroll
    for (int i = 0; i < 8; i++) {
        int row = bm + ((i < 4) ? (ty * 4 + i) : (ty * 4 + 64 + i - 4));
        *(float4*)(C + (size_t)row * N + bn + tx * 4) =
            make_float4(acc[i][0], acc[i][1], acc[i][2], acc[i][3]);
        *(float4*)(C + (size_t)row * N + bn + tx * 4 + 64) =
            make_float4(acc[i][4], acc[i][5], acc[i][6], acc[i][7]);
    }
}

// -------- 5) pnorm from diag of R: pnorm[p]^2 = sum_ij_valid R[u_p,u_p] --------
__global__ __launch_bounds__(256) void pnorm_kernel() {
    int p = threadIdx.x;
    int py = p >> 4, px = p & 15;
    float s = 0.f;
    #pragma unroll
    for (int ij = 0; ij < 9; ij++) {
        int di = ij / 3 - 1, dj = ij % 3 - 1;
        int y = py + di, x = px + dj;
        if ((unsigned)y < 16u && (unsigned)x < 16u) {
            int u = y * 16 + x;
            float r = 0.f;
            #pragma unroll
            for (int z = 0; z < 4; z++) r += g_S[z * 65536 + u * 256 + u];
            s += r;
        }
    }
    g_pnorm[p] = fmaxf(sqrtf(s), 1e-4f);
}

// ------ 6) fused score reconstruction (9-tap sum of R) + softmax over p per q ------
__global__ __launch_bounds__(256) void score_softmax_kernel() {
    int q = blockIdx.x;
    int qy = q >> 4, qx = q & 15;
    __shared__ float sr[9][256];
    __shared__ float red[256];
    __shared__ float snorm[256];
    int tid = threadIdx.x;
    snorm[tid] = g_pnorm[tid];
    #pragma unroll
    for (int ij = 0; ij < 9; ij++) {
        int di = ij / 3 - 1, dj = ij % 3 - 1;
        int y = qy + di, x = qx + dj;
        if ((unsigned)y < 16u && (unsigned)x < 16u) {
            int u = y * 16 + x;
            float v = 0.f;
            #pragma unroll
            for (int z = 0; z < 4; z++) v += g_S[z * 65536 + u * 256 + tid];
            sr[ij][tid] = v;
        } else sr[ij][tid] = 0.f;
    }
    __syncthreads();
    int p = tid, py = p >> 4, px = p & 15;
    float v = 0.f;
    #pragma unroll
    for (int ij = 0; ij < 9; ij++) {
        int di = ij / 3 - 1, dj = ij % 3 - 1;
        int y = py + di, x = px + dj;
        if ((unsigned)y < 16u && (unsigned)x < 16u) v += sr[ij][y * 16 + x];
    }
    v = v * 10.f / snorm[p];
    red[p] = v; __syncthreads();
    for (int s = 128; s > 0; s >>= 1) { if (p < s) red[p] = fmaxf(red[p], red[p + s]); __syncthreads(); }
    float mx = red[0]; __syncthreads();
    float e = __expf(v - mx);
    red[p] = e; __syncthreads();
    for (int s = 128; s > 0; s >>= 1) { if (p < s) red[p] += red[p + s]; __syncthreads(); }
    float inv = 1.f / red[0];
    g_attnT[q * 256 + p] = e * inv;   // [q][p], coalesced
}

// ---------------- 9) scatter deconv taps (T'[q][row]) -> out_32 pixel-major ----------------
__global__ __launch_bounds__(512) void ral_out_kernel() {
    int pix = blockIdx.x;
    int ho = pix >> 5, wo = pix & 31;
    int c = threadIdx.x;
    float acc = 0.f;
    for (int ki = (ho + 1) & 1; ki < 4; ki += 2) {
        int qy = (ho + 1 - ki) >> 1;
        if ((unsigned)qy >= 16u) continue;
        for (int kj = (wo + 1) & 1; kj < 4; kj += 2) {
            int qx = (wo + 1 - kj) >> 1;
            if ((unsigned)qx >= 16u) continue;
            int q = qy * 16 + qx;
            acc += g_T[(size_t)q * 8192 + (ki * 4 + kj) * 512 + c];
        }
    }
    g_out32T[(size_t)pix * 512 + c] = acc * 0.25f;
}

// ---------------- sum 4 split-K partials (gaussian) ----------------
__global__ __launch_bounds__(256) void reduce4_kernel(const float* __restrict__ in,
                                                      float* __restrict__ out, int n) {
    int i = blockIdx.x * 256 + threadIdx.x;
    out[i] = in[i] + in[n + i] + in[2 * n + i] + in[3 * n + i];
}

// ---------------- 11) CSA: per-position 3x3 patch softmax ----------------
__global__ __launch_bounds__(512) void csa_kernel() {
    int pos = blockIdx.x;
    int y = pos >> 5, x = pos & 31;
    int c = threadIdx.x;
    __shared__ float s_sum[16 * 9];
    __shared__ float s_a[9];
    float center = g_out32T[(size_t)pos * 512 + c];
    float sc = 1.f / (1.f + __expf(-center));
    float nb[9], pr[9];
    #pragma unroll
    for (int ij = 0; ij < 9; ij++) {
        int di = ij / 3 - 1, dj = ij % 3 - 1;
        int yy = y + di, xx = x + dj;
        bool ok = (unsigned)yy < 32u && (unsigned)xx < 32u;
        float v = ok ? g_out32T[(size_t)(yy * 32 + xx) * 512 + c] : 0.f;
        nb[ij] = v;
        float sn = ok ? 1.f / (1.f + __expf(-v)) : 0.f;
        pr[ij] = sc * sn;
    }
    #pragma unroll
    for (int ij = 0; ij < 9; ij++)
        #pragma unroll
        for (int o = 16; o > 0; o >>= 1) pr[ij] += __shfl_down_sync(0xFFFFFFFFu, pr[ij], o);
    int w = c >> 5, l = c & 31;
    if (l == 0) {
        #pragma unroll
        for (int ij = 0; ij < 9; ij++) s_sum[w * 9 + ij] = pr[ij];
    }
    __syncthreads();
    if (c < 9) {
        float t = 0.f;
        for (int w2 = 0; w2 < 16; w2++) t += s_sum[w2 * 9 + c];
        s_a[c] = t * (1.f / 512.f);
    }
    __syncthreads();
    if (c == 0) {
        float mx = s_a[0];
        for (int ij = 1; ij < 9; ij++) mx = fmaxf(mx, s_a[ij]);
        float sum = 0.f; float e[9];
        for (int ij = 0; ij < 9; ij++) { e[ij] = __expf(s_a[ij] - mx); sum += e[ij]; }
        float invs = 1.f / sum;
        for (int ij = 0; ij < 9; ij++) s_a[ij] = e[ij] * invs;
    }
    __syncthreads();
    float out = 0.f;
    #pragma unroll
    for (int ij = 0; ij < 9; ij++) out += s_a[ij] * nb[ij];
    g_z[512 * 1024 + (size_t)pos * 512 + c] = out;
}

// ------------- instance norm + leaky relu; sums npart split-K slices; optional concat copy ----
__global__ __launch_bounds__(256) void norm_leaky_kernel(
    const float* __restrict__ in, int npart, float* __restrict__ outA,
    const float* __restrict__ cpsrc, float* __restrict__ outB) {
    __shared__ float s_red[64];
    int c = blockIdx.x, tid = threadIdx.x;
    float v[4]; float s = 0.f, s2 = 0.f;
    #pragma unroll
    for (int q = 0; q < 4; q++) {
        int idx = c * 1024 + tid + q * 256;
        float acc = in[idx];
        for (int z = 1; z < npart; z++) acc += in[(size_t)z * 512 * 1024 + idx];
        v[q] = acc;
        s += acc; s2 += acc * acc;
    }
    blockReduce2(s, s2, s_red);
    float mu = s * (1.f / 1024.f);
    float inv = rsqrtf(s2 * (1.f / 1024.f) - mu * mu + 1e-5f);
    #pragma unroll
    for (int q = 0; q < 4; q++) {
        float f = (v[q] - mu) * inv;
        outA[c * 1024 + tid + q * 256] = f >= 0.f ? f : 0.2f * f;
    }
    if (cpsrc != nullptr) {
        #pragma unroll
        for (int q = 0; q < 4; q++)
            outB[c * 1024 + tid + q * 256] = cpsrc[c * 1024 + tid + q * 256];
    }
}

// ---------------- host ----------------
extern "C" void kernel_launch(void* const* d_in, const int* in_sizes, int n_in,
                              void* d_out, int out_size) {
    const float* x     = (const float*)d_in[0];
    const float* gus   = (const float*)d_in[1];
    const float* w_sk3 = (const float*)d_in[2];
    const float* b_sk3 = (const float*)d_in[3];
    const float* w_sk5 = (const float*)d_in[4];
    const float* b_sk5 = (const float*)d_in[5];
    const float* w_sk7 = (const float*)d_in[6];
    const float* b_sk7 = (const float*)d_in[7];
    const float* w_fc  = (const float*)d_in[8];
    const float* b_fc  = (const float*)d_in[9];
    const float* w_fc0 = (const float*)d_in[10];
    const float* b_fc0 = (const float*)d_in[11];
    const float* w_fc1 = (const float*)d_in[12];
    const float* b_fc1 = (const float*)d_in[13];
    const float* w_fc2 = (const float*)d_in[14];
    const float* b_fc2 = (const float*)d_in[15];
    const float* w_down = (const float*)d_in[16];
    const float* w_fuse = (const float*)d_in[17];

    float *fgsT, *S, *attnT, *T, *out32T, *z, *d1, *z2, *outres;
    cudaGetSymbolAddress((void**)&fgsT, g_fgsT);
    cudaGetSymbolAddress((void**)&S, g_S);
    cudaGetSymbolAddress((void**)&attnT, g_attnT);
    cudaGetSymbolAddress((void**)&T, g_T);
    cudaGetSymbolAddress((void**)&out32T, g_out32T);
    cudaGetSymbolAddress((void**)&z, g_z);
    cudaGetSymbolAddress((void**)&d1, g_d1);
    cudaGetSymbolAddress((void**)&z2, g_z2);
    cudaGetSymbolAddress((void**)&outres, g_outres);

    // SKConv all branches (conv + IN + relu + pixel sums)
    sk_conv_all<<<dim3(512, 3), 256>>>(x, w_sk3, b_sk3, w_sk5, b_sk5, w_sk7, b_sk7);
    // channel attention FC1 (parallel across 32 blocks)
    fz_kernel<<<32, 256>>>(w_fc, b_fc);
    // per-channel attention + combine -> out_res, fgsT
    combine_kernel<<<512, 256>>>(w_fc0, b_fc0, w_fc1, b_fc1, w_fc2, b_fc2);
    // RAL via Gram matrix: R = F^T F (256x256x512, split-K 4)
    gemm128<true, false><<<dim3(2, 2, 4), 256>>>(fgsT, fgsT, S, 256, 256, 512, 4);
    pnorm_kernel<<<1, 256>>>();
    score_softmax_kernel<<<256, 256>>>();
    gemm128<true, true><<<dim3(64, 2, 1), 256>>>(attnT, outres, T, 256, 8192, 256, 1); // T' = attnT * gather(bg)^T
    ral_out_kernel<<<1024, 512>>>();
    // gaussian einsum -> first half of z (split-K 4 into T scratch, then reduce)
    gemm128<false, false><<<dim3(4, 8, 4), 256>>>(gus, out32T, T, 1024, 512, 1024, 4);
    reduce4_kernel<<<2048, 256>>>(T, z, 1024 * 512);
    // CSA -> second half of z
    csa_kernel<<<1024, 512>>>();
    // down 1x1 conv (split-K 4) + IN + leaky, concat out_res
    gemm128<false, false><<<dim3(8, 4, 4), 256>>>(w_down, z, d1, 512, 1024, 1024, 4);
    norm_leaky_kernel<<<512, 256>>>(d1, 4, z2, outres, z2 + 512 * 1024);
    // fuse 1x1 conv (split-K 4) + IN + leaky -> output
    gemm128<false, false><<<dim3(8, 4, 4), 256>>>(w_fuse, z2, d1, 512, 1024, 1024, 4);
    norm_leaky_kernel<<<512, 256>>>(d1, 4, (float*)d_out, nullptr, nullptr);
}

// round 5
// speedup vs baseline: 1.9453x; 1.0495x over previous
#include <cuda_runtime.h>
#include <mma.h>
#include <cstddef>

using namespace nvcuda;

// ---------------- scratch (static __device__, no allocs) ----------------
__device__ float g_feas[3 * 512 * 1024];
__device__ float g_bsum[3 * 512];
__device__ float g_fz[32];
__device__ float g_outres[512 * 1024];
__device__ float g_fgsT[256 * 512];       // fg_small, pixel-major [pos][c]
__device__ float g_pnorm[256];
__device__ float g_S[32 * 256 * 256];     // split-K partials of R = F^T F
__device__ float g_R[256 * 256];          // reduced R
__device__ float g_attnT[256 * 256];      // attn transposed: [q][p]
__device__ float g_T[256 * 8192];         // T'[q][row]; reused for gaussian partials
__device__ float g_out32T[1024 * 512];    // post-RAL out_32, pixel-major
__device__ float g_z[1024 * 1024];        // concat(gus_out, out_csa)
__device__ float g_d1[4 * 512 * 1024];    // split-K partials of down/fuse
__device__ float g_z2[1024 * 1024];       // concat(leaky(norm(down)), out_res)

// ---------------- helpers ----------------
__device__ __forceinline__ void blockReduce2(float& s, float& s2, float* sm) {
    __syncthreads();
    int tid = threadIdx.x;
    #pragma unroll
    for (int o = 16; o > 0; o >>= 1) {
        s  += __shfl_down_sync(0xFFFFFFFFu, s, o);
        s2 += __shfl_down_sync(0xFFFFFFFFu, s2, o);
    }
    int w = tid >> 5, l = tid & 31;
    int nw = blockDim.x >> 5;
    if (l == 0) { sm[w] = s; sm[32 + w] = s2; }
    __syncthreads();
    if (tid < 32) {
        s  = (tid < nw) ? sm[tid] : 0.f;
        s2 = (tid < nw) ? sm[32 + tid] : 0.f;
        #pragma unroll
        for (int o = 16; o > 0; o >>= 1) {
            s  += __shfl_down_sync(0xFFFFFFFFu, s, o);
            s2 += __shfl_down_sync(0xFFFFFFFFu, s2, o);
        }
        if (tid == 0) { sm[0] = s; sm[32] = s2; }
    }
    __syncthreads();
    s = sm[0]; s2 = sm[32];
}

// ------- 1) SK grouped conv (zero-padded smem tile) + IN + relu -------
template <int KS>
__device__ __forceinline__ void sk_conv_impl(
    const float* __restrict__ x, const float* __restrict__ w,
    const float* __restrict__ bias, int branch,
    float* s_ch, float* s_w, float* s_red) {
    constexpr int PAD = KS / 2;
    constexpr int W = 32 + 2 * PAD;
    int oc = blockIdx.x;
    int tid = threadIdx.x;
    const float* xin = x + (size_t)(oc >> 4) * 16 * 1024;
    const float* wo = w + (size_t)oc * 16 * KS * KS;
    for (int i = tid; i < 16 * KS * KS; i += 256) s_w[i] = wo[i];
    for (int i = tid; i < W * W; i += 256) s_ch[i] = 0.f;

    float acc[4] = {0.f, 0.f, 0.f, 0.f};
    for (int ic = 0; ic < 16; ic++) {
        __syncthreads();
        for (int i = tid; i < 1024; i += 256) {
            int y = i >> 5, xx = i & 31;
            s_ch[(y + PAD) * W + xx + PAD] = xin[ic * 1024 + i];
        }
        __syncthreads();
        const float* wi = &s_w[ic * KS * KS];
        #pragma unroll
        for (int q = 0; q < 4; q++) {
            int p = tid + q * 256;
            int y = p >> 5, xx = p & 31;
            float a = acc[q];
            #pragma unroll
            for (int ky = 0; ky < KS; ky++) {
                const float* row = &s_ch[(y + ky) * W + xx];
                #pragma unroll
                for (int kx = 0; kx < KS; kx++)
                    a += row[kx] * wi[ky * KS + kx];
            }
            acc[q] = a;
        }
    }
    float b = bias[oc];
    float s = 0.f, s2 = 0.f;
    #pragma unroll
    for (int q = 0; q < 4; q++) { acc[q] += b; s += acc[q]; s2 += acc[q] * acc[q]; }
    blockReduce2(s, s2, s_red);
    float mu = s * (1.f / 1024.f);
    float var = s2 * (1.f / 1024.f) - mu * mu;
    float inv = rsqrtf(var + 1e-5f);
    float rs = 0.f;
    float* fo = &g_feas[(size_t)branch * 512 * 1024 + (size_t)oc * 1024];
    #pragma unroll
    for (int q = 0; q < 4; q++) {
        float r = (acc[q] - mu) * inv;
        r = fmaxf(r, 0.f);
        fo[tid + q * 256] = r;
        rs += r;
    }
    float dummy = 0.f;
    blockReduce2(rs, dummy, s_red);
    if (tid == 0) g_bsum[branch * 512 + oc] = rs;
}

__global__ __launch_bounds__(256) void sk_conv_all(
    const float* __restrict__ x,
    const float* __restrict__ w3, const float* __restrict__ b3,
    const float* __restrict__ w5, const float* __restrict__ b5,
    const float* __restrict__ w7, const float* __restrict__ b7) {
    __shared__ float s_ch[38 * 38];
    __shared__ float s_w[16 * 49];
    __shared__ float s_red[64];
    int br = blockIdx.y;
    if (br == 0)      sk_conv_impl<3>(x, w3, b3, 0, s_ch, s_w, s_red);
    else if (br == 1) sk_conv_impl<5>(x, w5, b5, 1, s_ch, s_w, s_red);
    else              sk_conv_impl<7>(x, w7, b7, 2, s_ch, s_w, s_red);
}

// ---------------- 2) FC1 ----------------
__global__ __launch_bounds__(256) void fz_kernel(
    const float* __restrict__ w_fc, const float* __restrict__ b_fc) {
    __shared__ float s_red[64];
    int j = blockIdx.x, tid = threadIdx.x;
    float s = 0.f;
    for (int c = tid; c < 512; c += 256) {
        float fs = (g_bsum[c] + g_bsum[512 + c] + g_bsum[1024 + c]) * (1.f / 1024.f);
        s += fs * w_fc[j * 512 + c];
    }
    float dummy = 0.f;
    blockReduce2(s, dummy, s_red);
    if (tid == 0) g_fz[j] = s + b_fc[j];
}

// ------- 3) per-channel branch attention + combine -> out_res; avg pool -> fgsT ------
__global__ __launch_bounds__(256) void combine_kernel(
    const float* __restrict__ w0, const float* __restrict__ b0,
    const float* __restrict__ w1, const float* __restrict__ b1,
    const float* __restrict__ w2, const float* __restrict__ b2) {
    int c = blockIdx.x, tid = threadIdx.x;
    __shared__ float s_fz[32];
    __shared__ float s_a[3];
    __shared__ float s_o[1024];
    if (tid < 32) s_fz[tid] = g_fz[tid];
    __syncthreads();
    int w = tid >> 5, l = tid & 31;
    if (w < 3) {
        const float* wt = (w == 0) ? w0 : (w == 1) ? w1 : w2;
        const float* bt = (w == 0) ? b0 : (w == 1) ? b1 : b2;
        float v = s_fz[l] * wt[c * 32 + l];
        #pragma unroll
        for (int o = 16; o > 0; o >>= 1) v += __shfl_down_sync(0xFFFFFFFFu, v, o);
        if (l == 0) s_a[w] = v + bt[c];
    }
    __syncthreads();
    float A0 = s_a[0], A1 = s_a[1], A2 = s_a[2];
    float mx = fmaxf(A0, fmaxf(A1, A2));
    float e0 = __expf(A0 - mx), e1 = __expf(A1 - mx), e2 = __expf(A2 - mx);
    float inv = 1.f / (e0 + e1 + e2);
    float a0 = e0 * inv, a1 = e1 * inv, a2 = e2 * inv;

    for (int i = tid; i < 1024; i += 256) {
        float v = a0 * g_feas[(size_t)c * 1024 + i]
                + a1 * g_feas[512 * 1024 + (size_t)c * 1024 + i]
                + a2 * g_feas[2 * 512 * 1024 + (size_t)c * 1024 + i];
        g_outres[c * 1024 + i] = v;
        s_o[i] = v;
    }
    __syncthreads();
    int py = tid >> 4, px = tid & 15;
    float p = 0.25f * (s_o[(2 * py) * 32 + 2 * px] + s_o[(2 * py) * 32 + 2 * px + 1] +
                       s_o[(2 * py + 1) * 32 + 2 * px] + s_o[(2 * py + 1) * 32 + 2 * px + 1]);
    g_fgsT[(size_t)tid * 512 + c] = p;
}

// ---- fp32 128x128-tile SGEMM (used for R), software-pipelined ----
template <bool BT, bool GATHER>
__global__ __launch_bounds__(256) void gemm128(
    const float* __restrict__ A, const float* __restrict__ B, float* __restrict__ C,
    int M, int N, int K, int ksplit) {
    __shared__ float As[16][132];
    __shared__ float Bs[16][132];
    int tid = threadIdx.x;
    int bm = blockIdx.y * 128, bn = blockIdx.x * 128;
    int kchunk = K / ksplit, k0 = blockIdx.z * kchunk, kend = k0 + kchunk;
    C += (size_t)blockIdx.z * M * N;
    int lr = tid >> 2, lc = (tid & 3) * 4;
    int brow = tid >> 5, bcol = (tid & 31) * 4;
    int tx = tid & 15, ty = tid >> 4;

    float4 pa[2], pb[2];
    auto loadA = [&](int kk) {
        #pragma unroll
        for (int h = 0; h < 2; h++)
            pa[h] = *(const float4*)(A + (size_t)(bm + lr + h * 64) * K + kk + lc);
    };
    auto loadB = [&](int kk) {
        if (BT) {
            #pragma unroll
            for (int h = 0; h < 2; h++)
                pb[h] = *(const float4*)(B + (size_t)(bn + lr + h * 64) * K + kk + lc);
        } else {
            #pragma unroll
            for (int h = 0; h < 2; h++)
                pb[h] = *(const float4*)(B + (size_t)(kk + brow + h * 8) * N + bn + bcol);
        }
    };
    auto storeTiles = [&]() {
        #pragma unroll
        for (int h = 0; h < 2; h++) {
            int r = lr + h * 64;
            As[lc + 0][r] = pa[h].x; As[lc + 1][r] = pa[h].y;
            As[lc + 2][r] = pa[h].z; As[lc + 3][r] = pa[h].w;
        }
        if (BT) {
            #pragma unroll
            for (int h = 0; h < 2; h++) {
                int n = lr + h * 64;
                Bs[lc + 0][n] = pb[h].x; Bs[lc + 1][n] = pb[h].y;
                Bs[lc + 2][n] = pb[h].z; Bs[lc + 3][n] = pb[h].w;
            }
        } else {
            #pragma unroll
            for (int h = 0; h < 2; h++)
                *(float4*)&Bs[brow + h * 8][bcol] = pb[h];
        }
    };

    float acc[8][8] = {};
    loadA(k0); loadB(k0);
    for (int kk = k0; kk < kend; kk += 16) {
        storeTiles();
        __syncthreads();
        if (kk + 16 < kend) { loadA(kk + 16); loadB(kk + 16); }
        #pragma unroll
        for (int k = 0; k < 16; k++) {
            float4 a0 = *(const float4*)&As[k][ty * 4];
            float4 a1 = *(const float4*)&As[k][ty * 4 + 64];
            float4 b0 = *(const float4*)&Bs[k][tx * 4];
            float4 b1 = *(const float4*)&Bs[k][tx * 4 + 64];
            float ar[8] = {a0.x, a0.y, a0.z, a0.w, a1.x, a1.y, a1.z, a1.w};
            float br[8] = {b0.x, b0.y, b0.z, b0.w, b1.x, b1.y, b1.z, b1.w};
            #pragma unroll
            for (int i = 0; i < 8; i++)
                #pragma unroll
                for (int jj = 0; jj < 8; jj++) acc[i][jj] += ar[i] * br[jj];
        }
        __syncthreads();
    }
    #pragma unroll
    for (int i = 0; i < 8; i++) {
        int row = bm + ((i < 4) ? (ty * 4 + i) : (ty * 4 + 64 + i - 4));
        *(float4*)(C + (size_t)row * N + bn + tx * 4) =
            make_float4(acc[i][0], acc[i][1], acc[i][2], acc[i][3]);
        *(float4*)(C + (size_t)row * N + bn + tx * 4 + 64) =
            make_float4(acc[i][4], acc[i][5], acc[i][6], acc[i][7]);
    }
}

// ---- tf32 WMMA 128x128-tile GEMM (tensor pipe), same staging/layouts as gemm128 ----
template <bool BT, bool GATHER>
__global__ __launch_bounds__(256) void gemm128_tf32(
    const float* __restrict__ A, const float* __restrict__ B, float* __restrict__ C,
    int M, int N, int K, int ksplit) {
    __shared__ float As[16][132];   // [k][m] -> col_major A frag, ld 132
    __shared__ float Bs[16][132];   // [k][n] -> row_major B frag, ld 132
    int tid = threadIdx.x;
    int bm = blockIdx.y * 128, bn = blockIdx.x * 128;
    int kchunk = K / ksplit, k0 = blockIdx.z * kchunk, kend = k0 + kchunk;
    C += (size_t)blockIdx.z * M * N;
    int lr = tid >> 2, lc = (tid & 3) * 4;
    int brow = tid >> 5, bcol = (tid & 31) * 4;

    float4 pa[2], pb[2];
    auto loadA = [&](int kk) {
        #pragma unroll
        for (int h = 0; h < 2; h++)
            pa[h] = *(const float4*)(A + (size_t)(bm + lr + h * 64) * K + kk + lc);
    };
    auto loadB = [&](int kk) {
        if (GATHER) {
            #pragma unroll
            for (int h = 0; h < 2; h++) {
                int n = bn + lr + h * 64;
                int combo = n >> 9, c = n & 511;
                int ki = combo >> 2, kj = combo & 3;
                float v[4];
                #pragma unroll
                for (int t = 0; t < 4; t++) {
                    int p = kk + lc + t;
                    int py = p >> 4, px = p & 15;
                    int r = 2 * py + ki - 1, col = 2 * px + kj - 1;
                    v[t] = ((unsigned)r < 32u && (unsigned)col < 32u)
                         ? B[c * 1024 + r * 32 + col] : 0.f;
                }
                pb[h] = make_float4(v[0], v[1], v[2], v[3]);
            }
        } else if (BT) {
            #pragma unroll
            for (int h = 0; h < 2; h++)
                pb[h] = *(const float4*)(B + (size_t)(bn + lr + h * 64) * K + kk + lc);
        } else {
            #pragma unroll
            for (int h = 0; h < 2; h++)
                pb[h] = *(const float4*)(B + (size_t)(kk + brow + h * 8) * N + bn + bcol);
        }
    };
    auto storeTiles = [&]() {
        #pragma unroll
        for (int h = 0; h < 2; h++) {
            int r = lr + h * 64;
            As[lc + 0][r] = pa[h].x; As[lc + 1][r] = pa[h].y;
            As[lc + 2][r] = pa[h].z; As[lc + 3][r] = pa[h].w;
        }
        if (BT || GATHER) {
            #pragma unroll
            for (int h = 0; h < 2; h++) {
                int n = lr + h * 64;
                Bs[lc + 0][n] = pb[h].x; Bs[lc + 1][n] = pb[h].y;
                Bs[lc + 2][n] = pb[h].z; Bs[lc + 3][n] = pb[h].w;
            }
        } else {
            #pragma unroll
            for (int h = 0; h < 2; h++)
                *(float4*)&Bs[brow + h * 8][bcol] = pb[h];
        }
    };

    // warp tiling: 8 warps -> 4 along M (32 rows each), 2 along N (64 cols each)
    int warp = tid >> 5;
    int wm = warp & 3, wn = warp >> 2;
    wmma::fragment<wmma::accumulator, 16, 16, 8, float> cf[2][4];
    #pragma unroll
    for (int i = 0; i < 2; i++)
        #pragma unroll
        for (int j = 0; j < 4; j++) wmma::fill_fragment(cf[i][j], 0.f);

    loadA(k0); loadB(k0);
    for (int kk = k0; kk < kend; kk += 16) {
        storeTiles();
        __syncthreads();
        if (kk + 16 < kend) { loadA(kk + 16); loadB(kk + 16); }
        #pragma unroll
        for (int ks = 0; ks < 16; ks += 8) {
            wmma::fragment<wmma::matrix_a, 16, 16, 8, wmma::precision::tf32, wmma::col_major> af[2];
            wmma::fragment<wmma::matrix_b, 16, 16, 8, wmma::precision::tf32, wmma::row_major> bf[4];
            #pragma unroll
            for (int i = 0; i < 2; i++) {
                wmma::load_matrix_sync(af[i], &As[ks][wm * 32 + i * 16], 132);
                #pragma unroll
                for (int t = 0; t < af[i].num_elements; t++)
                    af[i].x[t] = wmma::__float_to_tf32(af[i].x[t]);
            }
            #pragma unroll
            for (int j = 0; j < 4; j++) {
                wmma::load_matrix_sync(bf[j], &Bs[ks][wn * 64 + j * 16], 132);
                #pragma unroll
                for (int t = 0; t < bf[j].num_elements; t++)
                    bf[j].x[t] = wmma::__float_to_tf32(bf[j].x[t]);
            }
            #pragma unroll
            for (int i = 0; i < 2; i++)
                #pragma unroll
                for (int j = 0; j < 4; j++)
                    wmma::mma_sync(cf[i][j], af[i], bf[j], cf[i][j]);
        }
        __syncthreads();
    }
    #pragma unroll
    for (int i = 0; i < 2; i++)
        #pragma unroll
        for (int j = 0; j < 4; j++) {
            int row = bm + wm * 32 + i * 16;
            int col = bn + wn * 64 + j * 16;
            wmma::store_matrix_sync(C + (size_t)row * N + col, cf[i][j], N, wmma::mem_row_major);
        }
}

// ---------------- reduce npart split-K slices ----------------
__global__ __launch_bounds__(256) void reduceN_kernel(const float* __restrict__ in,
                                                      float* __restrict__ out,
                                                      int n, int npart) {
    int i = blockIdx.x * 256 + threadIdx.x;
    float s = in[i];
    for (int z = 1; z < npart; z++) s += in[(size_t)z * n + i];
    out[i] = s;
}

// -------- 5) pnorm from diag of R --------
__global__ __launch_bounds__(256) void pnorm_kernel() {
    int p = threadIdx.x;
    int py = p >> 4, px = p & 15;
    float s = 0.f;
    #pragma unroll
    for (int ij = 0; ij < 9; ij++) {
        int di = ij / 3 - 1, dj = ij % 3 - 1;
        int y = py + di, x = px + dj;
        if ((unsigned)y < 16u && (unsigned)x < 16u) {
            int u = y * 16 + x;
            s += g_R[u * 256 + u];
        }
    }
    g_pnorm[p] = fmaxf(sqrtf(s), 1e-4f);
}

// ------ 6) fused score reconstruction (9-tap sum of R) + softmax over p per q ------
__global__ __launch_bounds__(256) void score_softmax_kernel() {
    int q = blockIdx.x;
    int qy = q >> 4, qx = q & 15;
    __shared__ float sr[9][256];
    __shared__ float red[256];
    __shared__ float snorm[256];
    int tid = threadIdx.x;
    snorm[tid] = g_pnorm[tid];
    #pragma unroll
    for (int ij = 0; ij < 9; ij++) {
        int di = ij / 3 - 1, dj = ij % 3 - 1;
        int y = qy + di, x = qx + dj;
        sr[ij][tid] = ((unsigned)y < 16u && (unsigned)x < 16u)
                    ? g_R[(y * 16 + x) * 256 + tid] : 0.f;
    }
    __syncthreads();
    int p = tid, py = p >> 4, px = p & 15;
    float v = 0.f;
    #pragma unroll
    for (int ij = 0; ij < 9; ij++) {
        int di = ij / 3 - 1, dj = ij % 3 - 1;
        int y = py + di, x = px + dj;
        if ((unsigned)y < 16u && (unsigned)x < 16u) v += sr[ij][y * 16 + x];
    }
    v = v * 10.f / snorm[p];
    red[p] = v; __syncthreads();
    for (int s = 128; s > 0; s >>= 1) { if (p < s) red[p] = fmaxf(red[p], red[p + s]); __syncthreads(); }
    float mx = red[0]; __syncthreads();
    float e = __expf(v - mx);
    red[p] = e; __syncthreads();
    for (int s = 128; s > 0; s >>= 1) { if (p < s) red[p] += red[p + s]; __syncthreads(); }
    float inv = 1.f / red[0];
    g_attnT[q * 256 + p] = e * inv;
}

// ---------------- 9) scatter deconv taps -> out_32 pixel-major ----------------
__global__ __launch_bounds__(512) void ral_out_kernel() {
    int pix = blockIdx.x;
    int ho = pix >> 5, wo = pix & 31;
    int c = threadIdx.x;
    float acc = 0.f;
    for (int ki = (ho + 1) & 1; ki < 4; ki += 2) {
        int qy = (ho + 1 - ki) >> 1;
        if ((unsigned)qy >= 16u) continue;
        for (int kj = (wo + 1) & 1; kj < 4; kj += 2) {
            int qx = (wo + 1 - kj) >> 1;
            if ((unsigned)qx >= 16u) continue;
            int q = qy * 16 + qx;
            acc += g_T[(size_t)q * 8192 + (ki * 4 + kj) * 512 + c];
        }
    }
    g_out32T[(size_t)pix * 512 + c] = acc * 0.25f;
}

// ---------------- 11) CSA ----------------
__global__ __launch_bounds__(512) void csa_kernel() {
    int pos = blockIdx.x;
    int y = pos >> 5, x = pos & 31;
    int c = threadIdx.x;
    __shared__ float s_sum[16 * 9];
    __shared__ float s_a[9];
    float center = g_out32T[(size_t)pos * 512 + c];
    float sc = 1.f / (1.f + __expf(-center));
    float nb[9], pr[9];
    #pragma unroll
    for (int ij = 0; ij < 9; ij++) {
        int di = ij / 3 - 1, dj = ij % 3 - 1;
        int yy = y + di, xx = x + dj;
        bool ok = (unsigned)yy < 32u && (unsigned)xx < 32u;
        float v = ok ? g_out32T[(size_t)(yy * 32 + xx) * 512 + c] : 0.f;
        nb[ij] = v;
        float sn = ok ? 1.f / (1.f + __expf(-v)) : 0.f;
        pr[ij] = sc * sn;
    }
    #pragma unroll
    for (int ij = 0; ij < 9; ij++)
        #pragma unroll
        for (int o = 16; o > 0; o >>= 1) pr[ij] += __shfl_down_sync(0xFFFFFFFFu, pr[ij], o);
    int w = c >> 5, l = c & 31;
    if (l == 0) {
        #pragma unroll
        for (int ij = 0; ij < 9; ij++) s_sum[w * 9 + ij] = pr[ij];
    }
    __syncthreads();
    if (c < 9) {
        float t = 0.f;
        for (int w2 = 0; w2 < 16; w2++) t += s_sum[w2 * 9 + c];
        s_a[c] = t * (1.f / 512.f);
    }
    __syncthreads();
    if (c == 0) {
        float mx = s_a[0];
        for (int ij = 1; ij < 9; ij++) mx = fmaxf(mx, s_a[ij]);
        float sum = 0.f; float e[9];
        for (int ij = 0; ij < 9; ij++) { e[ij] = __expf(s_a[ij] - mx); sum += e[ij]; }
        float invs = 1.f / sum;
        for (int ij = 0; ij < 9; ij++) s_a[ij] = e[ij] * invs;
    }
    __syncthreads();
    float out = 0.f;
    #pragma unroll
    for (int ij = 0; ij < 9; ij++) out += s_a[ij] * nb[ij];
    g_z[512 * 1024 + (size_t)pos * 512 + c] = out;
}

// ------------- instance norm + leaky relu; sums npart slices; optional concat copy ----
__global__ __launch_bounds__(256) void norm_leaky_kernel(
    const float* __restrict__ in, int npart, float* __restrict__ outA,
    const float* __restrict__ cpsrc, float* __restrict__ outB) {
    __shared__ float s_red[64];
    int c = blockIdx.x, tid = threadIdx.x;
    float v[4]; float s = 0.f, s2 = 0.f;
    #pragma unroll
    for (int q = 0; q < 4; q++) {
        int idx = c * 1024 + tid + q * 256;
        float acc = in[idx];
        for (int z = 1; z < npart; z++) acc += in[(size_t)z * 512 * 1024 + idx];
        v[q] = acc;
        s += acc; s2 += acc * acc;
    }
    blockReduce2(s, s2, s_red);
    float mu = s * (1.f / 1024.f);
    float inv = rsqrtf(s2 * (1.f / 1024.f) - mu * mu + 1e-5f);
    #pragma unroll
    for (int q = 0; q < 4; q++) {
        float f = (v[q] - mu) * inv;
        outA[c * 1024 + tid + q * 256] = f >= 0.f ? f : 0.2f * f;
    }
    if (cpsrc != nullptr) {
        #pragma unroll
        for (int q = 0; q < 4; q++)
            outB[c * 1024 + tid + q * 256] = cpsrc[c * 1024 + tid + q * 256];
    }
}

// ---------------- host ----------------
extern "C" void kernel_launch(void* const* d_in, const int* in_sizes, int n_in,
                              void* d_out, int out_size) {
    const float* x     = (const float*)d_in[0];
    const float* gus   = (const float*)d_in[1];
    const float* w_sk3 = (const float*)d_in[2];
    const float* b_sk3 = (const float*)d_in[3];
    const float* w_sk5 = (const float*)d_in[4];
    const float* b_sk5 = (const float*)d_in[5];
    const float* w_sk7 = (const float*)d_in[6];
    const float* b_sk7 = (const float*)d_in[7];
    const float* w_fc  = (const float*)d_in[8];
    const float* b_fc  = (const float*)d_in[9];
    const float* w_fc0 = (const float*)d_in[10];
    const float* b_fc0 = (const float*)d_in[11];
    const float* w_fc1 = (const float*)d_in[12];
    const float* b_fc1 = (const float*)d_in[13];
    const float* w_fc2 = (const float*)d_in[14];
    const float* b_fc2 = (const float*)d_in[15];
    const float* w_down = (const float*)d_in[16];
    const float* w_fuse = (const float*)d_in[17];

    float *fgsT, *S, *R, *attnT, *T, *out32T, *z, *d1, *z2, *outres;
    cudaGetSymbolAddress((void**)&fgsT, g_fgsT);
    cudaGetSymbolAddress((void**)&S, g_S);
    cudaGetSymbolAddress((void**)&R, g_R);
    cudaGetSymbolAddress((void**)&attnT, g_attnT);
    cudaGetSymbolAddress((void**)&T, g_T);
    cudaGetSymbolAddress((void**)&out32T, g_out32T);
    cudaGetSymbolAddress((void**)&z, g_z);
    cudaGetSymbolAddress((void**)&d1, g_d1);
    cudaGetSymbolAddress((void**)&z2, g_z2);
    cudaGetSymbolAddress((void**)&outres, g_outres);

    // SKConv all branches
    sk_conv_all<<<dim3(512, 3), 256>>>(x, w_sk3, b_sk3, w_sk5, b_sk5, w_sk7, b_sk7);
    fz_kernel<<<32, 256>>>(w_fc, b_fc);
    combine_kernel<<<512, 256>>>(w_fc0, b_fc0, w_fc1, b_fc1, w_fc2, b_fc2);
    // RAL Gram matrix R = F^T F, split-K 32 to fill the chip (fp32 for precision)
    gemm128<true, false><<<dim3(2, 2, 32), 256>>>(fgsT, fgsT, S, 256, 256, 512, 32);
    reduceN_kernel<<<256, 256>>>(S, R, 256 * 256, 32);
    pnorm_kernel<<<1, 256>>>();
    score_softmax_kernel<<<256, 256>>>();
    // deconv-as-GEMM (tf32): T' = attnT * gather(bg)^T
    gemm128_tf32<true, true><<<dim3(64, 2, 1), 256>>>(attnT, outres, T, 256, 8192, 256, 1);
    ral_out_kernel<<<1024, 512>>>();
    // gaussian einsum (tf32, split-K 4)
    gemm128_tf32<false, false><<<dim3(4, 8, 4), 256>>>(gus, out32T, T, 1024, 512, 1024, 4);
    reduceN_kernel<<<2048, 256>>>(T, z, 1024 * 512, 4);
    // CSA -> second half of z
    csa_kernel<<<1024, 512>>>();
    // down 1x1 conv (tf32, split-K 4) + IN + leaky, concat out_res
    gemm128_tf32<false, false><<<dim3(8, 4, 4), 256>>>(w_down, z, d1, 512, 1024, 1024, 4);
    norm_leaky_kernel<<<512, 256>>>(d1, 4, z2, outres, z2 + 512 * 1024);
    // fuse 1x1 conv (tf32, split-K 4) + IN + leaky -> output
    gemm128_tf32<false, false><<<dim3(8, 4, 4), 256>>>(w_fuse, z2, d1, 512, 1024, 1024, 4);
    norm_leaky_kernel<<<512, 256>>>(d1, 4, (float*)d_out, nullptr, nullptr);
}

// round 7
// speedup vs baseline: 2.7711x; 1.4245x over previous
#include <cuda_runtime.h>
#include <cuda_bf16.h>
#include <mma.h>
#include <cstddef>

using namespace nvcuda;

// ---------------- scratch (static __device__, no allocs) ----------------
__device__ float g_feas[3 * 512 * 1024];
__device__ float g_bsum[3 * 512];
__device__ float g_fz[32];
__device__ float g_outres[512 * 1024];
__device__ float g_fgsT[256 * 512];       // fg_small, pixel-major [pos][c]
__device__ float g_pnorm[256];
__device__ float g_S[32 * 256 * 256];     // split-K partials of R = F^T F
__device__ float g_R[256 * 256];          // reduced R
__device__ float g_attnT[256 * 256];      // attn transposed: [q][p]
__device__ float g_T[256 * 8192];         // T'[q][row]; reused for gaussian partials
__device__ float g_out32T[1024 * 512];    // post-RAL out_32, pixel-major
__device__ float g_z[1024 * 1024];        // concat(gus_out, out_csa)
__device__ float g_d1[4 * 512 * 1024];    // split-K partials of down/fuse
__device__ float g_z2[1024 * 1024];       // concat(leaky(norm(down)), out_res)

// ---------------- helpers ----------------
__device__ __forceinline__ void blockReduce2(float& s, float& s2, float* sm) {
    __syncthreads();
    int tid = threadIdx.x;
    #pragma unroll
    for (int o = 16; o > 0; o >>= 1) {
        s  += __shfl_down_sync(0xFFFFFFFFu, s, o);
        s2 += __shfl_down_sync(0xFFFFFFFFu, s2, o);
    }
    int w = tid >> 5, l = tid & 31;
    int nw = blockDim.x >> 5;
    if (l == 0) { sm[w] = s; sm[32 + w] = s2; }
    __syncthreads();
    if (tid < 32) {
        s  = (tid < nw) ? sm[tid] : 0.f;
        s2 = (tid < nw) ? sm[32 + tid] : 0.f;
        #pragma unroll
        for (int o = 16; o > 0; o >>= 1) {
            s  += __shfl_down_sync(0xFFFFFFFFu, s, o);
            s2 += __shfl_down_sync(0xFFFFFFFFu, s2, o);
        }
        if (tid == 0) { sm[0] = s; sm[32] = s2; }
    }
    __syncthreads();
    s = sm[0]; s2 = sm[32];
}

// ------- 1) SK grouped conv: 128 thr, 8 adjacent px/thread, register sliding window -------
template <int KS>
__device__ __forceinline__ void sk_conv_impl(
    const float* __restrict__ x, const float* __restrict__ w,
    const float* __restrict__ bias, int branch,
    float* s_ch, float* s_w, float* s_red) {
    constexpr int PAD = KS / 2;
    constexpr int W = 32 + 2 * PAD;
    int oc = blockIdx.x;
    int tid = threadIdx.x;
    int y = tid >> 2, xq = (tid & 3) * 8;
    const float* xin = x + (size_t)(oc >> 4) * 16 * 1024;
    const float* wo = w + (size_t)oc * 16 * KS * KS;
    for (int i = tid; i < 16 * KS * KS; i += 128) s_w[i] = wo[i];
    for (int i = tid; i < W * W; i += 128) s_ch[i] = 0.f;

    float acc[8] = {0.f, 0.f, 0.f, 0.f, 0.f, 0.f, 0.f, 0.f};
    for (int ic = 0; ic < 16; ic++) {
        __syncthreads();
        for (int i = tid; i < 1024; i += 128) {
            int yy = i >> 5, xx = i & 31;
            s_ch[(yy + PAD) * W + xx + PAD] = xin[ic * 1024 + i];
        }
        __syncthreads();
        const float* wi = &s_w[ic * KS * KS];
        #pragma unroll
        for (int ky = 0; ky < KS; ky++) {
            const float* rowp = &s_ch[(y + ky) * W + xq];
            float r[KS + 7];
            #pragma unroll
            for (int j = 0; j < KS + 7; j++) r[j] = rowp[j];
            #pragma unroll
            for (int kx = 0; kx < KS; kx++) {
                float wv = wi[ky * KS + kx];
                #pragma unroll
                for (int t = 0; t < 8; t++) acc[t] += r[kx + t] * wv;
            }
        }
    }
    float b = bias[oc];
    float s = 0.f, s2 = 0.f;
    #pragma unroll
    for (int t = 0; t < 8; t++) { acc[t] += b; s += acc[t]; s2 += acc[t] * acc[t]; }
    blockReduce2(s, s2, s_red);
    float mu = s * (1.f / 1024.f);
    float var = s2 * (1.f / 1024.f) - mu * mu;
    float inv = rsqrtf(var + 1e-5f);
    float rs = 0.f;
    float* fo = &g_feas[(size_t)branch * 512 * 1024 + (size_t)oc * 1024];
    float rv[8];
    #pragma unroll
    for (int t = 0; t < 8; t++) {
        float r = (acc[t] - mu) * inv;
        r = fmaxf(r, 0.f);
        rv[t] = r;
        rs += r;
    }
    *(float4*)(fo + y * 32 + xq)     = make_float4(rv[0], rv[1], rv[2], rv[3]);
    *(float4*)(fo + y * 32 + xq + 4) = make_float4(rv[4], rv[5], rv[6], rv[7]);
    float dummy = 0.f;
    blockReduce2(rs, dummy, s_red);
    if (tid == 0) g_bsum[branch * 512 + oc] = rs;
}

__global__ __launch_bounds__(128) void sk_conv_all(
    const float* __restrict__ x,
    const float* __restrict__ w3, const float* __restrict__ b3,
    const float* __restrict__ w5, const float* __restrict__ b5,
    const float* __restrict__ w7, const float* __restrict__ b7) {
    __shared__ float s_ch[38 * 38];
    __shared__ float s_w[16 * 49];
    __shared__ float s_red[64];
    int br = blockIdx.y;
    if (br == 0)      sk_conv_impl<3>(x, w3, b3, 0, s_ch, s_w, s_red);
    else if (br == 1) sk_conv_impl<5>(x, w5, b5, 1, s_ch, s_w, s_red);
    else              sk_conv_impl<7>(x, w7, b7, 2, s_ch, s_w, s_red);
}

// ---------------- 2) FC1 ----------------
__global__ __launch_bounds__(256) void fz_kernel(
    const float* __restrict__ w_fc, const float* __restrict__ b_fc) {
    __shared__ float s_red[64];
    int j = blockIdx.x, tid = threadIdx.x;
    float s = 0.f;
    for (int c = tid; c < 512; c += 256) {
        float fs = (g_bsum[c] + g_bsum[512 + c] + g_bsum[1024 + c]) * (1.f / 1024.f);
        s += fs * w_fc[j * 512 + c];
    }
    float dummy = 0.f;
    blockReduce2(s, dummy, s_red);
    if (tid == 0) g_fz[j] = s + b_fc[j];
}

// ------- 3) per-channel branch attention + combine -> out_res; avg pool -> fgsT ------
__global__ __launch_bounds__(256) void combine_kernel(
    const float* __restrict__ w0, const float* __restrict__ b0,
    const float* __restrict__ w1, const float* __restrict__ b1,
    const float* __restrict__ w2, const float* __restrict__ b2) {
    int c = blockIdx.x, tid = threadIdx.x;
    __shared__ float s_fz[32];
    __shared__ float s_a[3];
    __shared__ float s_o[1024];
    if (tid < 32) s_fz[tid] = g_fz[tid];
    __syncthreads();
    int w = tid >> 5, l = tid & 31;
    if (w < 3) {
        const float* wt = (w == 0) ? w0 : (w == 1) ? w1 : w2;
        const float* bt = (w == 0) ? b0 : (w == 1) ? b1 : b2;
        float v = s_fz[l] * wt[c * 32 + l];
        #pragma unroll
        for (int o = 16; o > 0; o >>= 1) v += __shfl_down_sync(0xFFFFFFFFu, v, o);
        if (l == 0) s_a[w] = v + bt[c];
    }
    __syncthreads();
    float A0 = s_a[0], A1 = s_a[1], A2 = s_a[2];
    float mx = fmaxf(A0, fmaxf(A1, A2));
    float e0 = __expf(A0 - mx), e1 = __expf(A1 - mx), e2 = __expf(A2 - mx);
    float inv = 1.f / (e0 + e1 + e2);
    float a0 = e0 * inv, a1 = e1 * inv, a2 = e2 * inv;

    for (int i = tid; i < 1024; i += 256) {
        float v = a0 * g_feas[(size_t)c * 1024 + i]
                + a1 * g_feas[512 * 1024 + (size_t)c * 1024 + i]
                + a2 * g_feas[2 * 512 * 1024 + (size_t)c * 1024 + i];
        g_outres[c * 1024 + i] = v;
        s_o[i] = v;
    }
    __syncthreads();
    int py = tid >> 4, px = tid & 15;
    float p = 0.25f * (s_o[(2 * py) * 32 + 2 * px] + s_o[(2 * py) * 32 + 2 * px + 1] +
                       s_o[(2 * py + 1) * 32 + 2 * px] + s_o[(2 * py + 1) * 32 + 2 * px + 1]);
    g_fgsT[(size_t)tid * 512 + c] = p;
}

// ---- fp32 128x128-tile SGEMM (used for R only), software-pipelined ----
__global__ __launch_bounds__(256) void gemm128_nt(
    const float* __restrict__ A, const float* __restrict__ B, float* __restrict__ C,
    int M, int N, int K, int ksplit) {
    __shared__ float As[16][132];
    __shared__ float Bs[16][132];
    int tid = threadIdx.x;
    int bm = blockIdx.y * 128, bn = blockIdx.x * 128;
    int kchunk = K / ksplit, k0 = blockIdx.z * kchunk, kend = k0 + kchunk;
    C += (size_t)blockIdx.z * M * N;
    int lr = tid >> 2, lc = (tid & 3) * 4;
    int tx = tid & 15, ty = tid >> 4;

    float4 pa[2], pb[2];
    auto loadAB = [&](int kk) {
        #pragma unroll
        for (int h = 0; h < 2; h++) {
            pa[h] = *(const float4*)(A + (size_t)(bm + lr + h * 64) * K + kk + lc);
            pb[h] = *(const float4*)(B + (size_t)(bn + lr + h * 64) * K + kk + lc);
        }
    };
    auto storeTiles = [&]() {
        #pragma unroll
        for (int h = 0; h < 2; h++) {
            int r = lr + h * 64;
            As[lc + 0][r] = pa[h].x; As[lc + 1][r] = pa[h].y;
            As[lc + 2][r] = pa[h].z; As[lc + 3][r] = pa[h].w;
            Bs[lc + 0][r] = pb[h].x; Bs[lc + 1][r] = pb[h].y;
            Bs[lc + 2][r] = pb[h].z; Bs[lc + 3][r] = pb[h].w;
        }
    };

    float acc[8][8] = {};
    loadAB(k0);
    for (int kk = k0; kk < kend; kk += 16) {
        storeTiles();
        __syncthreads();
        if (kk + 16 < kend) loadAB(kk + 16);
        #pragma unroll
        for (int k = 0; k < 16; k++) {
            float4 a0 = *(const float4*)&As[k][ty * 4];
            float4 a1 = *(const float4*)&As[k][ty * 4 + 64];
            float4 b0 = *(const float4*)&Bs[k][tx * 4];
            float4 b1 = *(const float4*)&Bs[k][tx * 4 + 64];
            float ar[8] = {a0.x, a0.y, a0.z, a0.w, a1.x, a1.y, a1.z, a1.w};
            float br[8] = {b0.x, b0.y, b0.z, b0.w, b1.x, b1.y, b1.z, b1.w};
            #pragma unroll
            for (int i = 0; i < 8; i++)
                #pragma unroll
                for (int jj = 0; jj < 8; jj++) acc[i][jj] += ar[i] * br[jj];
        }
        __syncthreads();
    }
    #pragma unroll
    for (int i = 0; i < 8; i++) {
        int row = bm + ((i < 4) ? (ty * 4 + i) : (ty * 4 + 64 + i - 4));
        *(float4*)(C + (size_t)row * N + bn + tx * 4) =
            make_float4(acc[i][0], acc[i][1], acc[i][2], acc[i][3]);
        *(float4*)(C + (size_t)row * N + bn + tx * 4 + 64) =
            make_float4(acc[i][4], acc[i][5], acc[i][6], acc[i][7]);
    }
}

// ---- bf16x2-split WMMA 128x128-tile GEMM (3-mma Ootomo, ~fp32 accuracy) ----
//      BT=false: C=A(MxK)*B(KxN);  BT=true: C=A(MxK)*B(NxK)^T;  GATHER: deconv bg taps.
template <bool BT, bool GATHER>
__global__ __launch_bounds__(256) void gemm128_bf16(
    const float* __restrict__ A, const float* __restrict__ B, float* __restrict__ C,
    int M, int N, int K, int ksplit) {
    __shared__ __nv_bfloat16 Ah[16][136], Al[16][136];
    __shared__ __nv_bfloat16 Bh[16][136], Bl[16][136];
    int tid = threadIdx.x;
    int bm = blockIdx.y * 128, bn = blockIdx.x * 128;
    int kchunk = K / ksplit, k0 = blockIdx.z * kchunk, kend = k0 + kchunk;
    C += (size_t)blockIdx.z * M * N;
    int lr = tid >> 2, lc = (tid & 3) * 4;
    int brow = tid >> 5, bcol = (tid & 31) * 4;

    float4 pa[2], pb[2];
    auto loadA = [&](int kk) {
        #pragma unroll
        for (int h = 0; h < 2; h++)
            pa[h] = *(const float4*)(A + (size_t)(bm + lr + h * 64) * K + kk + lc);
    };
    auto loadB = [&](int kk) {
        if (GATHER) {
            #pragma unroll
            for (int h = 0; h < 2; h++) {
                int n = bn + lr + h * 64;
                int combo = n >> 9, c = n & 511;
                int ki = combo >> 2, kj = combo & 3;
                float v[4];
                #pragma unroll
                for (int t = 0; t < 4; t++) {
                    int p = kk + lc + t;
                    int py = p >> 4, px = p & 15;
                    int r = 2 * py + ki - 1, col = 2 * px + kj - 1;
                    v[t] = ((unsigned)r < 32u && (unsigned)col < 32u)
                         ? B[c * 1024 + r * 32 + col] : 0.f;
                }
                pb[h] = make_float4(v[0], v[1], v[2], v[3]);
            }
        } else if (BT) {
            #pragma unroll
            for (int h = 0; h < 2; h++)
                pb[h] = *(const float4*)(B + (size_t)(bn + lr + h * 64) * K + kk + lc);
        } else {
            #pragma unroll
            for (int h = 0; h < 2; h++)
                pb[h] = *(const float4*)(B + (size_t)(kk + brow + h * 8) * N + bn + bcol);
        }
    };
    auto splitStore = [](__nv_bfloat16* hi, __nv_bfloat16* lo, float v) {
        __nv_bfloat16 h = __float2bfloat16(v);
        *hi = h;
        *lo = __float2bfloat16(v - __bfloat162float(h));
    };
    auto storeTiles = [&]() {
        #pragma unroll
        for (int h = 0; h < 2; h++) {
            int r = lr + h * 64;
            float va[4] = {pa[h].x, pa[h].y, pa[h].z, pa[h].w};
            #pragma unroll
            for (int t = 0; t < 4; t++)
                splitStore(&Ah[lc + t][r], &Al[lc + t][r], va[t]);
        }
        if (BT || GATHER) {
            #pragma unroll
            for (int h = 0; h < 2; h++) {
                int n = lr + h * 64;
                float vb[4] = {pb[h].x, pb[h].y, pb[h].z, pb[h].w};
                #pragma unroll
                for (int t = 0; t < 4; t++)
                    splitStore(&Bh[lc + t][n], &Bl[lc + t][n], vb[t]);
            }
        } else {
            #pragma unroll
            for (int h = 0; h < 2; h++) {
                int r = brow + h * 8;
                float vb[4] = {pb[h].x, pb[h].y, pb[h].z, pb[h].w};
                #pragma unroll
                for (int t = 0; t < 4; t++)
                    splitStore(&Bh[r][bcol + t], &Bl[r][bcol + t], vb[t]);
            }
        }
    };

    // warp tiling: 8 warps -> 4 along M (32 rows), 2 along N (64 cols)
    int warp = tid >> 5;
    int wm = warp & 3, wn = warp >> 2;
    wmma::fragment<wmma::accumulator, 16, 16, 16, float> cf[2][4];
    #pragma unroll
    for (int i = 0; i < 2; i++)
        #pragma unroll
        for (int j = 0; j < 4; j++) wmma::fill_fragment(cf[i][j], 0.f);

    loadA(k0); loadB(k0);
    for (int kk = k0; kk < kend; kk += 16) {
        storeTiles();
        __syncthreads();
        if (kk + 16 < kend) { loadA(kk + 16); loadB(kk + 16); }
        wmma::fragment<wmma::matrix_a, 16, 16, 16, __nv_bfloat16, wmma::col_major> afh[2], afl[2];
        wmma::fragment<wmma::matrix_b, 16, 16, 16, __nv_bfloat16, wmma::row_major> bfh[4], bfl[4];
        #pragma unroll
        for (int i = 0; i < 2; i++) {
            wmma::load_matrix_sync(afh[i], &Ah[0][wm * 32 + i * 16], 136);
            wmma::load_matrix_sync(afl[i], &Al[0][wm * 32 + i * 16], 136);
        }
        #pragma unroll
        for (int j = 0; j < 4; j++) {
            wmma::load_matrix_sync(bfh[j], &Bh[0][wn * 64 + j * 16], 136);
            wmma::load_matrix_sync(bfl[j], &Bl[0][wn * 64 + j * 16], 136);
        }
        #pragma unroll
        for (int i = 0; i < 2; i++)
            #pragma unroll
            for (int j = 0; j < 4; j++) {
                wmma::mma_sync(cf[i][j], afh[i], bfh[j], cf[i][j]);
                wmma::mma_sync(cf[i][j], afh[i], bfl[j], cf[i][j]);
                wmma::mma_sync(cf[i][j], afl[i], bfh[j], cf[i][j]);
            }
        __syncthreads();
    }
    #pragma unroll
    for (int i = 0; i < 2; i++)
        #pragma unroll
        for (int j = 0; j < 4; j++) {
            int row = bm + wm * 32 + i * 16;
            int col = bn + wn * 64 + j * 16;
            wmma::store_matrix_sync(C + (size_t)row * N + col, cf[i][j], N, wmma::mem_row_major);
        }
}

// ---------------- reduce npart split-K slices ----------------
__global__ __launch_bounds__(256) void reduceN_kernel(const float* __restrict__ in,
                                                      float* __restrict__ out,
                                                      int n, int npart) {
    int i = blockIdx.x * 256 + threadIdx.x;
    float s = in[i];
    for (int z = 1; z < npart; z++) s += in[(size_t)z * n + i];
    out[i] = s;
}

// -------- 5) pnorm from diag of R --------
__global__ __launch_bounds__(256) void pnorm_kernel() {
    int p = threadIdx.x;
    int py = p >> 4, px = p & 15;
    float s = 0.f;
    #pragma unroll
    for (int ij = 0; ij < 9; ij++) {
        int di = ij / 3 - 1, dj = ij % 3 - 1;
        int y = py + di, x = px + dj;
        if ((unsigned)y < 16u && (unsigned)x < 16u) {
            int u = y * 16 + x;
            s += g_R[u * 256 + u];
        }
    }
    g_pnorm[p] = fmaxf(sqrtf(s), 1e-4f);
}

// ------ 6) fused score reconstruction (9-tap sum of R) + softmax over p per q ------
__global__ __launch_bounds__(256) void score_softmax_kernel() {
    int q = blockIdx.x;
    int qy = q >> 4, qx = q & 15;
    __shared__ float sr[9][256];
    __shared__ float red[256];
    __shared__ float snorm[256];
    int tid = threadIdx.x;
    snorm[tid] = g_pnorm[tid];
    #pragma unroll
    for (int ij = 0; ij < 9; ij++) {
        int di = ij / 3 - 1, dj = ij % 3 - 1;
        int y = qy + di, x = qx + dj;
        sr[ij][tid] = ((unsigned)y < 16u && (unsigned)x < 16u)
                    ? g_R[(y * 16 + x) * 256 + tid] : 0.f;
    }
    __syncthreads();
    int p = tid, py = p >> 4, px = p & 15;
    float v = 0.f;
    #pragma unroll
    for (int ij = 0; ij < 9; ij++) {
        int di = ij / 3 - 1, dj = ij % 3 - 1;
        int y = py + di, x = px + dj;
        if ((unsigned)y < 16u && (unsigned)x < 16u) v += sr[ij][y * 16 + x];
    }
    v = v * 10.f / snorm[p];
    red[p] = v; __syncthreads();
    for (int s = 128; s > 0; s >>= 1) { if (p < s) red[p] = fmaxf(red[p], red[p + s]); __syncthreads(); }
    float mx = red[0]; __syncthreads();
    float e = __expf(v - mx);
    red[p] = e; __syncthreads();
    for (int s = 128; s > 0; s >>= 1) { if (p < s) red[p] += red[p + s]; __syncthreads(); }
    float inv = 1.f / red[0];
    g_attnT[q * 256 + p] = e * inv;
}

// ---------------- 9) scatter deconv taps -> out_32 pixel-major ----------------
__global__ __launch_bounds__(512) void ral_out_kernel() {
    int pix = blockIdx.x;
    int ho = pix >> 5, wo = pix & 31;
    int c = threadIdx.x;
    float acc = 0.f;
    for (int ki = (ho + 1) & 1; ki < 4; ki += 2) {
        int qy = (ho + 1 - ki) >> 1;
        if ((unsigned)qy >= 16u) continue;
        for (int kj = (wo + 1) & 1; kj < 4; kj += 2) {
            int qx = (wo + 1 - kj) >> 1;
            if ((unsigned)qx >= 16u) continue;
            int q = qy * 16 + qx;
            acc += g_T[(size_t)q * 8192 + (ki * 4 + kj) * 512 + c];
        }
    }
    g_out32T[(size_t)pix * 512 + c] = acc * 0.25f;
}

// ---------------- 11) CSA ----------------
__global__ __launch_bounds__(512) void csa_kernel() {
    int pos = blockIdx.x;
    int y = pos >> 5, x = pos & 31;
    int c = threadIdx.x;
    __shared__ float s_sum[16 * 9];
    __shared__ float s_a[9];
    float center = g_out32T[(size_t)pos * 512 + c];
    float sc = 1.f / (1.f + __expf(-center));
    float nb[9], pr[9];
    #pragma unroll
    for (int ij = 0; ij < 9; ij++) {
        int di = ij / 3 - 1, dj = ij % 3 - 1;
        int yy = y + di, xx = x + dj;
        bool ok = (unsigned)yy < 32u && (unsigned)xx < 32u;
        float v = ok ? g_out32T[(size_t)(yy * 32 + xx) * 512 + c] : 0.f;
        nb[ij] = v;
        float sn = ok ? 1.f / (1.f + __expf(-v)) : 0.f;
        pr[ij] = sc * sn;
    }
    #pragma unroll
    for (int ij = 0; ij < 9; ij++)
        #pragma unroll
        for (int o = 16; o > 0; o >>= 1) pr[ij] += __shfl_down_sync(0xFFFFFFFFu, pr[ij], o);
    int w = c >> 5, l = c & 31;
    if (l == 0) {
        #pragma unroll
        for (int ij = 0; ij < 9; ij++) s_sum[w * 9 + ij] = pr[ij];
    }
    __syncthreads();
    if (c < 9) {
        float t = 0.f;
        for (int w2 = 0; w2 < 16; w2++) t += s_sum[w2 * 9 + c];
        s_a[c] = t * (1.f / 512.f);
    }
    __syncthreads();
    if (c == 0) {
        float mx = s_a[0];
        for (int ij = 1; ij < 9; ij++) mx = fmaxf(mx, s_a[ij]);
        float sum = 0.f; float e[9];
        for (int ij = 0; ij < 9; ij++) { e[ij] = __expf(s_a[ij] - mx); sum += e[ij]; }
        float invs = 1.f / sum;
        for (int ij = 0; ij < 9; ij++) s_a[ij] = e[ij] * invs;
    }
    __syncthreads();
    float out = 0.f;
    #pragma unroll
    for (int ij = 0; ij < 9; ij++) out += s_a[ij] * nb[ij];
    g_z[512 * 1024 + (size_t)pos * 512 + c] = out;
}

// ------------- instance norm + leaky relu; sums npart slices; optional concat copy ----
__global__ __launch_bounds__(256) void norm_leaky_kernel(
    const float* __restrict__ in, int npart, float* __restrict__ outA,
    const float* __restrict__ cpsrc, float* __restrict__ outB) {
    __shared__ float s_red[64];
    int c = blockIdx.x, tid = threadIdx.x;
    float v[4]; float s = 0.f, s2 = 0.f;
    #pragma unroll
    for (int q = 0; q < 4; q++) {
        int idx = c * 1024 + tid + q * 256;
        float acc = in[idx];
        for (int z = 1; z < npart; z++) acc += in[(size_t)z * 512 * 1024 + idx];
        v[q] = acc;
        s += acc; s2 += acc * acc;
    }
    blockReduce2(s, s2, s_red);
    float mu = s * (1.f / 1024.f);
    float inv = rsqrtf(s2 * (1.f / 1024.f) - mu * mu + 1e-5f);
    #pragma unroll
    for (int q = 0; q < 4; q++) {
        float f = (v[q] - mu) * inv;
        outA[c * 1024 + tid + q * 256] = f >= 0.f ? f : 0.2f * f;
    }
    if (cpsrc != nullptr) {
        #pragma unroll
        for (int q = 0; q < 4; q++)
            outB[c * 1024 + tid + q * 256] = cpsrc[c * 1024 + tid + q * 256];
    }
}

// ---------------- host ----------------
extern "C" void kernel_launch(void* const* d_in, const int* in_sizes, int n_in,
                              void* d_out, int out_size) {
    const float* x     = (const float*)d_in[0];
    const float* gus   = (const float*)d_in[1];
    const float* w_sk3 = (const float*)d_in[2];
    const float* b_sk3 = (const float*)d_in[3];
    const float* w_sk5 = (const float*)d_in[4];
    const float* b_sk5 = (const float*)d_in[5];
    const float* w_sk7 = (const float*)d_in[6];
    const float* b_sk7 = (const float*)d_in[7];
    const float* w_fc  = (const float*)d_in[8];
    const float* b_fc  = (const float*)d_in[9];
    const float* w_fc0 = (const float*)d_in[10];
    const float* b_fc0 = (const float*)d_in[11];
    const float* w_fc1 = (const float*)d_in[12];
    const float* b_fc1 = (const float*)d_in[13];
    const float* w_fc2 = (const float*)d_in[14];
    const float* b_fc2 = (const float*)d_in[15];
    const float* w_down = (const float*)d_in[16];
    const float* w_fuse = (const float*)d_in[17];

    float *fgsT, *S, *R, *attnT, *T, *out32T, *z, *d1, *z2, *outres;
    cudaGetSymbolAddress((void**)&fgsT, g_fgsT);
    cudaGetSymbolAddress((void**)&S, g_S);
    cudaGetSymbolAddress((void**)&R, g_R);
    cudaGetSymbolAddress((void**)&attnT, g_attnT);
    cudaGetSymbolAddress((void**)&T, g_T);
    cudaGetSymbolAddress((void**)&out32T, g_out32T);
    cudaGetSymbolAddress((void**)&z, g_z);
    cudaGetSymbolAddress((void**)&d1, g_d1);
    cudaGetSymbolAddress((void**)&z2, g_z2);
    cudaGetSymbolAddress((void**)&outres, g_outres);

    // SKConv all branches (128 thr, 8 px/thread)
    sk_conv_all<<<dim3(512, 3), 128>>>(x, w_sk3, b_sk3, w_sk5, b_sk5, w_sk7, b_sk7);
    fz_kernel<<<32, 256>>>(w_fc, b_fc);
    combine_kernel<<<512, 256>>>(w_fc0, b_fc0, w_fc1, b_fc1, w_fc2, b_fc2);
    // RAL Gram matrix R = F^T F (fp32, split-K 32)
    gemm128_nt<<<dim3(2, 2, 32), 256>>>(fgsT, fgsT, S, 256, 256, 512, 32);
    reduceN_kernel<<<256, 256>>>(S, R, 256 * 256, 32);
    pnorm_kernel<<<1, 256>>>();
    score_softmax_kernel<<<256, 256>>>();
    // deconv-as-GEMM (bf16x2): T' = attnT * gather(bg)^T
    gemm128_bf16<true, true><<<dim3(64, 2, 1), 256>>>(attnT, outres, T, 256, 8192, 256, 1);
    ral_out_kernel<<<1024, 512>>>();
    // gaussian einsum (bf16x2, split-K 4)
    gemm128_bf16<false, false><<<dim3(4, 8, 4), 256>>>(gus, out32T, T, 1024, 512, 1024, 4);
    reduceN_kernel<<<2048, 256>>>(T, z, 1024 * 512, 4);
    // CSA -> second half of z
    csa_kernel<<<1024, 512>>>();
    // down 1x1 conv (bf16x2, split-K 4) + IN + leaky, concat out_res
    gemm128_bf16<false, false><<<dim3(8, 4, 4), 256>>>(w_down, z, d1, 512, 1024, 1024, 4);
    norm_leaky_kernel<<<512, 256>>>(d1, 4, z2, outres, z2 + 512 * 1024);
    // fuse 1x1 conv (bf16x2, split-K 4) + IN + leaky -> output
    gemm128_bf16<false, false><<<dim3(8, 4, 4), 256>>>(w_fuse, z2, d1, 512, 1024, 1024, 4);
    norm_leaky_kernel<<<512, 256>>>(d1, 4, (float*)d_out, nullptr, nullptr);
}